// round 2
// baseline (speedup 1.0000x reference)
#include <cuda_runtime.h>
#include <cuda_bf16.h>
#include <math.h>

#define Bq 512
#define Nq 101
#define Dq 128
#define Hq 128
#define NHq 8
#define HDq 16
#define Tq 140

// Scratch (allocation-free rule: __device__ globals)
__device__ float g_K [Bq * Nq * Hq];
__device__ float g_V [Bq * Nq * Hq];
__device__ float g_Kp[Bq * Nq * Hq];
__device__ float g_pool[Tq * Bq * Hq];

// ---------------------------------------------------------------------------
// P1: K/V/Kp = enc @ W  (rows = B*N = 51712, 32 rows per block)
// ---------------------------------------------------------------------------
#define ROWS_P1 32
__global__ void precomp_kvp(const float* __restrict__ enc,
                            const float* __restrict__ Wk,
                            const float* __restrict__ Wv,
                            const float* __restrict__ Wpk) {
    __shared__ float es[ROWS_P1 * 128];
    const int t = threadIdx.x;           // 128 threads
    const int row0 = blockIdx.x * ROWS_P1;
    const int nrows = Bq * Nq;

    for (int i = t; i < ROWS_P1 * 128; i += 128) {
        int r = row0 + (i >> 7);
        es[i] = (r < nrows) ? enc[r * 128 + (i & 127)] : 0.f;
    }
    __syncthreads();

    const int j = t;
    for (int m = 0; m < 3; m++) {
        const float* W = (m == 0) ? Wk : ((m == 1) ? Wv : Wpk);
        float* out     = (m == 0) ? g_K : ((m == 1) ? g_V : g_Kp);
        float acc[ROWS_P1];
#pragma unroll
        for (int r = 0; r < ROWS_P1; r++) acc[r] = 0.f;
        for (int d = 0; d < 128; d++) {
            float w = W[d * 128 + j];
#pragma unroll
            for (int r = 0; r < ROWS_P1; r++) acc[r] += es[r * 128 + d] * w;
        }
        for (int r = 0; r < ROWS_P1; r++) {
            int rr = row0 + r;
            if (rr < nrows) out[rr * 128 + j] = acc[r];
        }
    }
}

// ---------------------------------------------------------------------------
// P2: pool chain. g_pool[s][b][:] = pool_b @ W_fc1^(s+1)
// ---------------------------------------------------------------------------
__global__ void precomp_pool(const float* __restrict__ pool,
                             const float* __restrict__ Wfc1) {
    extern __shared__ float sm2[];   // 128*128 W + 128 p
    float* Ws = sm2;
    __shared__ float p[128];
    const int b = blockIdx.x;
    const int t = threadIdx.x;       // 128 threads
    for (int i = t; i < 128 * 128; i += 128) Ws[i] = Wfc1[i];
    p[t] = pool[b * 128 + t];
    __syncthreads();
    for (int s = 0; s < Tq; s++) {
        float acc = 0.f;
#pragma unroll 8
        for (int i = 0; i < 128; i++) acc += p[i] * Ws[i * 128 + t];
        __syncthreads();
        p[t] = acc;
        g_pool[(s * Bq + b) * 128 + t] = acc;
        __syncthreads();
    }
}

// ---------------------------------------------------------------------------
// Main sequential decoder: one block per batch row, 256 threads.
// ---------------------------------------------------------------------------
__global__ __launch_bounds__(256, 1)
void decoder_main(const float* __restrict__ enc,
                  const float* __restrict__ capc,
                  const float* __restrict__ demand,
                  const float* __restrict__ Wfc,     // (129,128)
                  const float* __restrict__ Ww,      // (128,128)
                  const float* __restrict__ Wat,     // (128,128)
                  float* __restrict__ out) {
    extern __shared__ float sm[];
    float* Ks     = sm;                    // 101*128
    float* Vs     = Ks  + Nq * 128;
    float* Kps    = Vs  + Nq * 128;
    float* compat = Kps + Nq * 128;        // 8*101

    __shared__ float red[256];
    __shared__ float vA[128];              // dec / glimpse_pre
    __shared__ float vB[128];              // Q   / glimpse
    __shared__ float xin[128];
    __shared__ float logits[104];
    __shared__ float dem_s[104];
    __shared__ unsigned char maskA[104];
    __shared__ unsigned char mask1A[104];
    __shared__ float s_dyn, s_cap0, s_logp;
    __shared__ int   s_idx, s_cnt;

    const int t    = threadIdx.x;
    const int b    = blockIdx.x;
    const int j    = t & 127;
    const int half = t >> 7;

    // --- register-resident weight slices -----------------------------------
    float wfc_r[65];
    float ww_r[64];
    float wat_r[64];
    if (half == 0) {
#pragma unroll
        for (int k = 0; k < 65; k++) wfc_r[k] = Wfc[k * 128 + j];
    } else {
#pragma unroll
        for (int k = 0; k < 64; k++) wfc_r[k] = Wfc[(65 + k) * 128 + j];
        wfc_r[64] = 0.f;
    }
#pragma unroll
    for (int k = 0; k < 64; k++) ww_r[k]  = Ww [(half * 64 + k) * 128 + j];
#pragma unroll
    for (int k = 0; k < 64; k++) wat_r[k] = Wat[(half * 64 + k) * 128 + j];

    // --- load per-batch K/V/Kp tiles into smem -----------------------------
    {
        const float4* gk  = (const float4*)(g_K  + (size_t)b * Nq * 128);
        const float4* gv  = (const float4*)(g_V  + (size_t)b * Nq * 128);
        const float4* gkp = (const float4*)(g_Kp + (size_t)b * Nq * 128);
        float4* sk  = (float4*)Ks;
        float4* sv  = (float4*)Vs;
        float4* skp = (float4*)Kps;
        for (int i = t; i < Nq * 32; i += 256) {
            sk[i]  = gk[i];
            sv[i]  = gv[i];
            skp[i] = gkp[i];
        }
    }

    // --- initial state -----------------------------------------------------
    if (t == 0) {
        s_cap0 = capc[0];
        s_dyn  = capc[b];
        s_logp = 0.f;
        s_cnt  = 0;
    }
    if (t < Nq) dem_s[t] = demand[b * Nq + t];
    if (t < 128) xin[t] = enc[((size_t)b * Nq) * 128 + t];
    __syncthreads();
    if (t < Nq) {
        mask1A[t] = (t == 0) ? 1 : 0;
        maskA[t]  = ((t == 0) || (dem_s[t] > s_dyn)) ? 1 : 0;
    }
    __syncthreads();

    // =========================== step loop =================================
    for (int step = 0; step < Tq; step++) {
        // ---- dec = [xin, dyn] @ W_fc + pool_n -----------------------------
        float acc = 0.f;
        if (half == 0) {
#pragma unroll
            for (int k = 0; k < 65; k++) acc += xin[k] * wfc_r[k];
        } else {
#pragma unroll
            for (int k = 0; k < 63; k++) acc += xin[65 + k] * wfc_r[k];
            acc += s_dyn * wfc_r[63];
        }
        red[t] = acc;
        __syncthreads();
        if (t < 128)
            vA[t] = red[t] + red[t + 128] + g_pool[(step * Bq + b) * 128 + t];
        __syncthreads();

        // ---- Q = dec @ W_w ------------------------------------------------
        acc = 0.f;
#pragma unroll
        for (int k = 0; k < 64; k++) acc += vA[half * 64 + k] * ww_r[k];
        red[t] = acc;
        __syncthreads();
        if (t < 128) vB[t] = red[t] + red[t + 128];
        __syncthreads();

        // ---- compat[h][n] = Q_h . K_h[n] / 4 ------------------------------
        for (int p = t; p < NHq * Nq; p += 256) {
            int n = p >> 3, h = p & 7;
            const float* kr = &Ks[n * 128 + h * HDq];
            const float* qr = &vB[h * HDq];
            float a = 0.f;
#pragma unroll
            for (int d = 0; d < HDq; d++) a += qr[d] * kr[d];
            compat[h * Nq + n] = a * 0.25f;
        }
        __syncthreads();

        // ---- masked softmax per head (warp w = head w) --------------------
        {
            const int w = t >> 5, lane = t & 31;
            float mx = -INFINITY;
            for (int n = lane; n < Nq; n += 32) {
                float v = maskA[n] ? -INFINITY : compat[w * Nq + n];
                mx = fmaxf(mx, v);
            }
#pragma unroll
            for (int o = 16; o; o >>= 1) mx = fmaxf(mx, __shfl_xor_sync(0xffffffffu, mx, o));
            float sum = 0.f;
            for (int n = lane; n < Nq; n += 32) {
                float v = maskA[n] ? 0.f : expf(compat[w * Nq + n] - mx);
                compat[w * Nq + n] = v;
                sum += v;
            }
#pragma unroll
            for (int o = 16; o; o >>= 1) sum += __shfl_xor_sync(0xffffffffu, sum, o);
            float inv = 1.f / sum;
            for (int n = lane; n < Nq; n += 32) compat[w * Nq + n] *= inv;
        }
        __syncthreads();

        // ---- glimpse_pre[o] = sum_n sc[h][n] * V[n][o] --------------------
        {
            const int o = j;
            const int h = o >> 4;
            float a = 0.f;
            if (half == 0) {
                for (int n = 0; n < 51; n++) a += compat[h * Nq + n] * Vs[n * 128 + o];
            } else {
                for (int n = 51; n < Nq; n++) a += compat[h * Nq + n] * Vs[n * 128 + o];
            }
            red[t] = a;
        }
        __syncthreads();
        if (t < 128) vA[t] = red[t] + red[t + 128];
        __syncthreads();

        // ---- g = glimpse_pre @ W_attnfc -----------------------------------
        acc = 0.f;
#pragma unroll
        for (int k = 0; k < 64; k++) acc += vA[half * 64 + k] * wat_r[k];
        red[t] = acc;
        __syncthreads();
        if (t < 128) vB[t] = red[t] + red[t + 128];
        __syncthreads();

        // ---- logits[n] = mask ? -inf : 10*tanh( g.Kp[n] / sqrt(128) ) -----
        {
            const int n2 = t >> 1, hf = t & 1;
            float a = 0.f;
            if (n2 < Nq) {
                const float* kp = &Kps[n2 * 128 + hf * 64];
                const float* gg = &vB[hf * 64];
#pragma unroll 16
                for (int k = 0; k < 64; k++) a += gg[k] * kp[k];
            }
            red[t] = a;
        }
        __syncthreads();
        if (t < Nq) {
            float c2 = (red[2 * t] + red[2 * t + 1]) * 0.08838834764831845f;
            logits[t] = maskA[t] ? -INFINITY : 10.f * tanhf(c2);
        }
        __syncthreads();

        // ---- argmax + log-softmax + state update (warp 0) -----------------
        if (t < 32) {
            float bv = -INFINITY; int bi = Nq;
            for (int n = t; n < Nq; n += 32) {
                float v = logits[n];
                if (v > bv || (v == bv && n < bi)) { bv = v; bi = n; }
            }
#pragma unroll
            for (int o = 16; o; o >>= 1) {
                float ov = __shfl_xor_sync(0xffffffffu, bv, o);
                int   oi = __shfl_xor_sync(0xffffffffu, bi, o);
                if (ov > bv || (ov == bv && oi < bi)) { bv = ov; bi = oi; }
            }
            float s = 0.f;
            for (int n = t; n < Nq; n += 32) s += expf(logits[n] - bv);
#pragma unroll
            for (int o = 16; o; o >>= 1) s += __shfl_xor_sync(0xffffffffu, s, o);

            if (t == 0) {
                // log_p (pre-update is_done check)
                if (s_cnt < Nq - 1) s_logp += -logf(s);
                s_idx = bi;
                out[b * Tq + step] = (float)bi;         // action
                // state update
                float nd = (bi == 0) ? s_cap0 : (s_dyn - dem_s[bi]);
                s_dyn = nd;
                if (bi > 0 && !mask1A[bi]) { mask1A[bi] = 1; s_cnt++; }
                mask1A[0] = (bi == 0) ? 1 : 0;
            }
        }
        __syncthreads();
        if (t < Nq)
            maskA[t] = (mask1A[t] || (dem_s[t] > s_dyn)) ? 1 : 0;
        __syncthreads();
        if (t < 32) {
            int open = 0;
            for (int n = t; n < Nq; n += 32) open |= (maskA[n] == 0);
            open = __any_sync(0xffffffffu, open);
            if (t == 0 && !open) maskA[0] = 0;
        }
        // new input row
        if (t < 128) xin[t] = enc[((size_t)b * Nq + s_idx) * 128 + t];
        __syncthreads();
    }

    if (t == 0) out[Bq * Tq + b] = s_logp;
}

// ---------------------------------------------------------------------------
extern "C" void kernel_launch(void* const* d_in, const int* in_sizes, int n_in,
                              void* d_out, int out_size) {
    const float *enc = nullptr, *pool = nullptr, *capc = nullptr, *dem = nullptr, *Wfc = nullptr;
    const float* w16[8] = {nullptr};
    int nw = 0;
    for (int i = 0; i < n_in; i++) {
        int s = in_sizes[i];
        if      (s == Bq * Nq * Dq) enc  = (const float*)d_in[i];
        else if (s == Bq * Hq)      pool = (const float*)d_in[i];
        else if (s == Bq)           capc = (const float*)d_in[i];
        else if (s == Bq * Nq)      dem  = (const float*)d_in[i];
        else if (s == (Hq + 1) * Hq) Wfc = (const float*)d_in[i];
        else if (s == Hq * Hq) { if (nw < 8) w16[nw++] = (const float*)d_in[i]; }
    }
    // dict order: W_fc1, W_w, W_k, W_v, W_attnfc, W_pk
    const float* Wfc1 = w16[0];
    const float* Ww   = w16[1];
    const float* Wk   = w16[2];
    const float* Wv   = w16[3];
    const float* Wat  = w16[4];
    const float* Wpk  = w16[5];

    const int smem_main = (Nq * 128 * 3 + NHq * Nq) * (int)sizeof(float);
    cudaFuncSetAttribute(decoder_main, cudaFuncAttributeMaxDynamicSharedMemorySize, smem_main);
    cudaFuncSetAttribute(precomp_pool, cudaFuncAttributeMaxDynamicSharedMemorySize, 128 * 128 * 4);

    precomp_kvp<<<(Bq * Nq + ROWS_P1 - 1) / ROWS_P1, 128>>>(enc, Wk, Wv, Wpk);
    precomp_pool<<<Bq, 128, 128 * 128 * 4>>>(pool, Wfc1);
    decoder_main<<<Bq, 256, smem_main>>>(enc, capc, dem, Wfc, Ww, Wat, (float*)d_out);
}

// round 3
// speedup vs baseline: 1.5935x; 1.5935x over previous
#include <cuda_runtime.h>
#include <cuda_bf16.h>
#include <math.h>

#define Bq 512
#define Nq 101
#define Dq 128
#define Hq 128
#define NHq 8
#define HDq 16
#define Tq 140

// Scratch (allocation-free rule: __device__ globals)
__device__ float g_K [Bq * Nq * Hq];
__device__ float g_V [Bq * Nq * Hq];
__device__ float g_Kp[Bq * Nq * Hq];
__device__ float g_pool[Tq * Bq * Hq];

// ---------------------------------------------------------------------------
// P1: K/V/Kp = enc @ W  (rows = B*N = 51712, 32 rows per block)
// ---------------------------------------------------------------------------
#define ROWS_P1 32
__global__ void precomp_kvp(const float* __restrict__ enc,
                            const float* __restrict__ Wk,
                            const float* __restrict__ Wv,
                            const float* __restrict__ Wpk) {
    __shared__ float es[ROWS_P1 * 128];
    const int t = threadIdx.x;           // 128 threads
    const int row0 = blockIdx.x * ROWS_P1;
    const int nrows = Bq * Nq;

    for (int i = t; i < ROWS_P1 * 128; i += 128) {
        int r = row0 + (i >> 7);
        es[i] = (r < nrows) ? enc[r * 128 + (i & 127)] : 0.f;
    }
    __syncthreads();

    const int j = t;
    for (int m = 0; m < 3; m++) {
        const float* W = (m == 0) ? Wk : ((m == 1) ? Wv : Wpk);
        float* out     = (m == 0) ? g_K : ((m == 1) ? g_V : g_Kp);
        float acc[ROWS_P1];
#pragma unroll
        for (int r = 0; r < ROWS_P1; r++) acc[r] = 0.f;
        for (int d = 0; d < 128; d++) {
            float w = W[d * 128 + j];
#pragma unroll
            for (int r = 0; r < ROWS_P1; r++) acc[r] += es[r * 128 + d] * w;
        }
        for (int r = 0; r < ROWS_P1; r++) {
            int rr = row0 + r;
            if (rr < nrows) out[rr * 128 + j] = acc[r];
        }
    }
}

// ---------------------------------------------------------------------------
// P2: pool chain. g_pool[s][b][:] = pool_b @ W_fc1^(s+1)
// ---------------------------------------------------------------------------
__global__ void precomp_pool(const float* __restrict__ pool,
                             const float* __restrict__ Wfc1) {
    extern __shared__ float sm2[];   // 128*128 W + 128 p
    float* Ws = sm2;
    __shared__ float p[128];
    const int b = blockIdx.x;
    const int t = threadIdx.x;       // 128 threads
    for (int i = t; i < 128 * 128; i += 128) Ws[i] = Wfc1[i];
    p[t] = pool[b * 128 + t];
    __syncthreads();
    for (int s = 0; s < Tq; s++) {
        float acc = 0.f;
#pragma unroll 8
        for (int i = 0; i < 128; i++) acc += p[i] * Ws[i * 128 + t];
        __syncthreads();
        p[t] = acc;
        g_pool[(s * Bq + b) * 128 + t] = acc;
        __syncthreads();
    }
}

// ---------------------------------------------------------------------------
// Main sequential decoder: one block per batch row, 256 threads.
// ---------------------------------------------------------------------------
__global__ __launch_bounds__(256, 1)
void decoder_main(const float* __restrict__ enc,
                  const float* __restrict__ capc,
                  const float* __restrict__ demand,
                  const float* __restrict__ Wfc,     // (129,128)
                  const float* __restrict__ Ww,      // (128,128)
                  const float* __restrict__ Wat,     // (128,128)
                  float* __restrict__ out) {
    extern __shared__ float sm[];
    float* Ks     = sm;                    // 101*128
    float* Vs     = Ks  + Nq * 128;
    float* Kps    = Vs  + Nq * 128;
    float* compat = Kps + Nq * 128;        // 8*101

    __shared__ float red[256];
    __shared__ float vA[128];              // dec / glimpse_pre
    __shared__ float vB[128];              // Q   / glimpse
    __shared__ float xin[128];
    __shared__ float logits[104];
    __shared__ float dem_s[104];
    __shared__ unsigned char maskA[104];
    __shared__ unsigned char mask1A[104];
    __shared__ float s_dyn, s_cap0, s_logp;
    __shared__ int   s_idx, s_cnt;

    const int t    = threadIdx.x;
    const int b    = blockIdx.x;
    const int j    = t & 127;
    const int half = t >> 7;

    // --- register-resident weight slices -----------------------------------
    float wfc_r[65];
    float ww_r[64];
    float wat_r[64];
    if (half == 0) {
#pragma unroll
        for (int k = 0; k < 65; k++) wfc_r[k] = Wfc[k * 128 + j];
    } else {
#pragma unroll
        for (int k = 0; k < 64; k++) wfc_r[k] = Wfc[(65 + k) * 128 + j];
        wfc_r[64] = 0.f;
    }
#pragma unroll
    for (int k = 0; k < 64; k++) ww_r[k]  = Ww [(half * 64 + k) * 128 + j];
#pragma unroll
    for (int k = 0; k < 64; k++) wat_r[k] = Wat[(half * 64 + k) * 128 + j];

    // --- load per-batch K/V/Kp tiles into smem -----------------------------
    {
        const float4* gk  = (const float4*)(g_K  + (size_t)b * Nq * 128);
        const float4* gv  = (const float4*)(g_V  + (size_t)b * Nq * 128);
        const float4* gkp = (const float4*)(g_Kp + (size_t)b * Nq * 128);
        float4* sk  = (float4*)Ks;
        float4* sv  = (float4*)Vs;
        float4* skp = (float4*)Kps;
        for (int i = t; i < Nq * 32; i += 256) {
            sk[i]  = gk[i];
            sv[i]  = gv[i];
            skp[i] = gkp[i];
        }
    }

    // --- initial state -----------------------------------------------------
    if (t == 0) {
        s_cap0 = capc[0];
        s_dyn  = capc[b];
        s_logp = 0.f;
        s_cnt  = 0;
    }
    if (t < Nq) dem_s[t] = demand[b * Nq + t];
    if (t < 128) xin[t] = enc[((size_t)b * Nq) * 128 + t];
    __syncthreads();
    if (t < Nq) {
        mask1A[t] = (t == 0) ? 1 : 0;
        maskA[t]  = ((t == 0) || (dem_s[t] > s_dyn)) ? 1 : 0;
    }
    __syncthreads();

    // =========================== step loop =================================
    for (int step = 0; step < Tq; step++) {
        // ---- dec = [xin, dyn] @ W_fc + pool_n -----------------------------
        float acc = 0.f;
        if (half == 0) {
#pragma unroll
            for (int k = 0; k < 65; k++) acc += xin[k] * wfc_r[k];
        } else {
#pragma unroll
            for (int k = 0; k < 63; k++) acc += xin[65 + k] * wfc_r[k];
            acc += s_dyn * wfc_r[63];
        }
        red[t] = acc;
        __syncthreads();
        if (t < 128)
            vA[t] = red[t] + red[t + 128] + g_pool[(step * Bq + b) * 128 + t];
        __syncthreads();

        // ---- Q = dec @ W_w ------------------------------------------------
        acc = 0.f;
#pragma unroll
        for (int k = 0; k < 64; k++) acc += vA[half * 64 + k] * ww_r[k];
        red[t] = acc;
        __syncthreads();
        if (t < 128) vB[t] = red[t] + red[t + 128];
        __syncthreads();

        // ---- compat[h][n] = Q_h . K_h[n] / 4 ------------------------------
        for (int p = t; p < NHq * Nq; p += 256) {
            int n = p >> 3, h = p & 7;
            const float* kr = &Ks[n * 128 + h * HDq];
            const float* qr = &vB[h * HDq];
            float a = 0.f;
#pragma unroll
            for (int d = 0; d < HDq; d++) a += qr[d] * kr[d];
            compat[h * Nq + n] = a * 0.25f;
        }
        __syncthreads();

        // ---- masked softmax per head (warp w = head w) --------------------
        {
            const int w = t >> 5, lane = t & 31;
            float mx = -INFINITY;
            for (int n = lane; n < Nq; n += 32) {
                float v = maskA[n] ? -INFINITY : compat[w * Nq + n];
                mx = fmaxf(mx, v);
            }
#pragma unroll
            for (int o = 16; o; o >>= 1) mx = fmaxf(mx, __shfl_xor_sync(0xffffffffu, mx, o));
            float sum = 0.f;
            for (int n = lane; n < Nq; n += 32) {
                float v = maskA[n] ? 0.f : expf(compat[w * Nq + n] - mx);
                compat[w * Nq + n] = v;
                sum += v;
            }
#pragma unroll
            for (int o = 16; o; o >>= 1) sum += __shfl_xor_sync(0xffffffffu, sum, o);
            float inv = 1.f / sum;
            for (int n = lane; n < Nq; n += 32) compat[w * Nq + n] *= inv;
        }
        __syncthreads();

        // ---- glimpse_pre[o] = sum_n sc[h][n] * V[n][o] --------------------
        {
            const int o = j;
            const int h = o >> 4;
            float a = 0.f;
            if (half == 0) {
                for (int n = 0; n < 51; n++) a += compat[h * Nq + n] * Vs[n * 128 + o];
            } else {
                for (int n = 51; n < Nq; n++) a += compat[h * Nq + n] * Vs[n * 128 + o];
            }
            red[t] = a;
        }
        __syncthreads();
        if (t < 128) vA[t] = red[t] + red[t + 128];
        __syncthreads();

        // ---- g = glimpse_pre @ W_attnfc -----------------------------------
        acc = 0.f;
#pragma unroll
        for (int k = 0; k < 64; k++) acc += vA[half * 64 + k] * wat_r[k];
        red[t] = acc;
        __syncthreads();
        if (t < 128) vB[t] = red[t] + red[t + 128];
        __syncthreads();

        // ---- logits[n] = mask ? -inf : 10*tanh( g.Kp[n] / sqrt(128) ) -----
        {
            const int n2 = t >> 1, hf = t & 1;
            float a = 0.f;
            if (n2 < Nq) {
                const float* kp = &Kps[n2 * 128 + hf * 64];
                const float* gg = &vB[hf * 64];
#pragma unroll 16
                for (int k = 0; k < 64; k++) a += gg[k] * kp[k];
            }
            red[t] = a;
        }
        __syncthreads();
        if (t < Nq) {
            float c2 = (red[2 * t] + red[2 * t + 1]) * 0.08838834764831845f;
            logits[t] = maskA[t] ? -INFINITY : 10.f * tanhf(c2);
        }
        __syncthreads();

        // ---- argmax + log-softmax + state update (warp 0) -----------------
        if (t < 32) {
            float bv = -INFINITY; int bi = Nq;
            for (int n = t; n < Nq; n += 32) {
                float v = logits[n];
                if (v > bv || (v == bv && n < bi)) { bv = v; bi = n; }
            }
#pragma unroll
            for (int o = 16; o; o >>= 1) {
                float ov = __shfl_xor_sync(0xffffffffu, bv, o);
                int   oi = __shfl_xor_sync(0xffffffffu, bi, o);
                if (ov > bv || (ov == bv && oi < bi)) { bv = ov; bi = oi; }
            }
            float s = 0.f;
            for (int n = t; n < Nq; n += 32) s += expf(logits[n] - bv);
#pragma unroll
            for (int o = 16; o; o >>= 1) s += __shfl_xor_sync(0xffffffffu, s, o);

            if (t == 0) {
                // log_p (pre-update is_done check)
                if (s_cnt < Nq - 1) s_logp += -logf(s);
                s_idx = bi;
                out[b * Tq + step] = (float)bi;         // action
                // state update
                float nd = (bi == 0) ? s_cap0 : (s_dyn - dem_s[bi]);
                s_dyn = nd;
                if (bi > 0 && !mask1A[bi]) { mask1A[bi] = 1; s_cnt++; }
                mask1A[0] = (bi == 0) ? 1 : 0;
            }
        }
        __syncthreads();
        if (t < Nq)
            maskA[t] = (mask1A[t] || (dem_s[t] > s_dyn)) ? 1 : 0;
        __syncthreads();
        if (t < 32) {
            int open = 0;
            for (int n = t; n < Nq; n += 32) open |= (maskA[n] == 0);
            open = __any_sync(0xffffffffu, open);
            if (t == 0 && !open) maskA[0] = 0;
        }
        // new input row
        if (t < 128) xin[t] = enc[((size_t)b * Nq + s_idx) * 128 + t];
        __syncthreads();
    }

    if (t == 0) out[Bq * Tq + b] = s_logp;
}

// ---------------------------------------------------------------------------
extern "C" void kernel_launch(void* const* d_in, const int* in_sizes, int n_in,
                              void* d_out, int out_size) {
    const float *enc = nullptr, *pool = nullptr, *capc = nullptr, *dem = nullptr, *Wfc = nullptr;
    const float* w16[8] = {nullptr};
    int nw = 0;
    for (int i = 0; i < n_in; i++) {
        int s = in_sizes[i];
        if      (s == Bq * Nq * Dq) enc  = (const float*)d_in[i];
        else if (s == Bq * Hq)      pool = (const float*)d_in[i];
        else if (s == Bq)           capc = (const float*)d_in[i];
        else if (s == Bq * Nq)      dem  = (const float*)d_in[i];
        else if (s == (Hq + 1) * Hq) Wfc = (const float*)d_in[i];
        else if (s == Hq * Hq) { if (nw < 8) w16[nw++] = (const float*)d_in[i]; }
    }
    // dict order: W_fc1, W_w, W_k, W_v, W_attnfc, W_pk
    const float* Wfc1 = w16[0];
    const float* Ww   = w16[1];
    const float* Wk   = w16[2];
    const float* Wv   = w16[3];
    const float* Wat  = w16[4];
    const float* Wpk  = w16[5];

    const int smem_main = (Nq * 128 * 3 + NHq * Nq) * (int)sizeof(float);
    cudaFuncSetAttribute(decoder_main, cudaFuncAttributeMaxDynamicSharedMemorySize, smem_main);
    cudaFuncSetAttribute(precomp_pool, cudaFuncAttributeMaxDynamicSharedMemorySize, 128 * 128 * 4);

    precomp_kvp<<<(Bq * Nq + ROWS_P1 - 1) / ROWS_P1, 128>>>(enc, Wk, Wv, Wpk);
    precomp_pool<<<Bq, 128, 128 * 128 * 4>>>(pool, Wfc1);
    decoder_main<<<Bq, 256, smem_main>>>(enc, capc, dem, Wfc, Ww, Wat, (float*)d_out);
}

// round 5
// speedup vs baseline: 3.0520x; 1.9153x over previous
#include <cuda_runtime.h>
#include <cuda_bf16.h>
#include <math.h>

#define Bq 512
#define Nq 101
#define Hq 128
#define Tq 140
#define NP 104
#define NP4 26

// __device__ scratch (allocation-free rule)
__device__ float g_Wfw [129 * 128];                 // Wfc @ Ww
__device__ float g_Wpk2[128 * 128];                 // Wpk @ Wat^T
__device__ float g_poolW[(size_t)Bq * Tq * 128];    // pool@Wfc1^(s+1)@Ww

// ---------------------------------------------------------------------------
// P0: fold weights. blocks 0..128 -> Wfw rows; 129..256 -> Wpk2 rows.
// ---------------------------------------------------------------------------
__global__ void precomp0(const float* __restrict__ Wfc, const float* __restrict__ Ww,
                         const float* __restrict__ Wat, const float* __restrict__ Wpk) {
    __shared__ __align__(16) float row[128];
    const int t = threadIdx.x, bidx = blockIdx.x;
    if (bidx < 129) {
        row[t] = Wfc[bidx * 128 + t];
        __syncthreads();
        const float4* r4 = (const float4*)row;
        float a = 0.f;
        for (int k4 = 0; k4 < 32; k4++) {
            float4 r = r4[k4];
            a += r.x * Ww[(4 * k4 + 0) * 128 + t] + r.y * Ww[(4 * k4 + 1) * 128 + t]
               + r.z * Ww[(4 * k4 + 2) * 128 + t] + r.w * Ww[(4 * k4 + 3) * 128 + t];
        }
        g_Wfw[bidx * 128 + t] = a;
    } else {
        const int d = bidx - 129;
        row[t] = Wpk[d * 128 + t];
        __syncthreads();
        const float4* r4 = (const float4*)row;
        const float4* w4 = (const float4*)(Wat + t * 128);   // Wat[h=t][o]
        float a = 0.f;
        for (int k4 = 0; k4 < 32; k4++) {
            float4 r = r4[k4]; float4 wv = w4[k4];
            a += r.x * wv.x + r.y * wv.y + r.z * wv.z + r.w * wv.w;
        }
        g_Wpk2[d * 128 + t] = a;   // Wpk2[d][h]
    }
}

// ---------------------------------------------------------------------------
// P2: pool chain folded through Ww. 2 batches/block, weights in registers.
// ---------------------------------------------------------------------------
__global__ __launch_bounds__(256)
void precomp2(const float* __restrict__ pool, const float* __restrict__ Wfc1,
              const float* __restrict__ Ww) {
    __shared__ __align__(16) float pA[128], pB[128];
    __shared__ float red2[256], red3[256];
    const int t = threadIdx.x, j = t & 127, kh = t >> 7;
    const int b0 = blockIdx.x * 2;
    float wf[64], wq[64];
#pragma unroll
    for (int k = 0; k < 64; k++) {
        wf[k] = Wfc1[(kh * 64 + k) * 128 + j];
        wq[k] = Ww  [(kh * 64 + k) * 128 + j];
    }
    if (t < 128) { pA[t] = pool[b0 * 128 + t]; pB[t] = pool[(b0 + 1) * 128 + t]; }
    __syncthreads();
    for (int s = 0; s < Tq; s++) {
        const float4* pa4 = (const float4*)pA; const float4* pb4 = (const float4*)pB;
        float a0 = 0.f, a1 = 0.f;
#pragma unroll
        for (int k4 = 0; k4 < 16; k4++) {
            float4 xa = pa4[kh * 16 + k4], xb = pb4[kh * 16 + k4];
            a0 += xa.x * wf[4*k4] + xa.y * wf[4*k4+1] + xa.z * wf[4*k4+2] + xa.w * wf[4*k4+3];
            a1 += xb.x * wf[4*k4] + xb.y * wf[4*k4+1] + xb.z * wf[4*k4+2] + xb.w * wf[4*k4+3];
        }
        red2[t] = a0; red3[t] = a1;
        __syncthreads();
        if (t < 128) { pA[t] = red2[t] + red2[t + 128]; pB[t] = red3[t] + red3[t + 128]; }
        __syncthreads();
        a0 = 0.f; a1 = 0.f;
#pragma unroll
        for (int k4 = 0; k4 < 16; k4++) {
            float4 xa = pa4[kh * 16 + k4], xb = pb4[kh * 16 + k4];
            a0 += xa.x * wq[4*k4] + xa.y * wq[4*k4+1] + xa.z * wq[4*k4+2] + xa.w * wq[4*k4+3];
            a1 += xb.x * wq[4*k4] + xb.y * wq[4*k4+1] + xb.z * wq[4*k4+2] + xb.w * wq[4*k4+3];
        }
        red2[t] = a0; red3[t] = a1;
        __syncthreads();
        if (t < 128) {
            g_poolW[((size_t)b0 * Tq + s) * 128 + t]       = red2[t] + red2[t + 128];
            g_poolW[((size_t)(b0 + 1) * Tq + s) * 128 + t] = red3[t] + red3[t + 128];
        }
        __syncthreads();
    }
}

// ---------------------------------------------------------------------------
// prologue matmul helper: one chunk (<=17 rows) of one output column
// ---------------------------------------------------------------------------
__device__ __forceinline__ void mm_chunk(const float4* __restrict__ E4,
                                         const float* __restrict__ Wj,
                                         int n0, int c0, int cn, float* acc) {
#pragma unroll
    for (int r = 0; r < 17; r++) acc[r] = 0.f;
    for (int d4 = 0; d4 < 32; d4++) {
        float w0 = Wj[(4 * d4 + 0) * 128], w1 = Wj[(4 * d4 + 1) * 128];
        float w2 = Wj[(4 * d4 + 2) * 128], w3 = Wj[(4 * d4 + 3) * 128];
#pragma unroll
        for (int r = 0; r < 17; r++) if (r < cn) {
            float4 e = E4[(n0 + c0 + r) * 32 + d4];
            acc[r] = fmaf(e.x, w0, fmaf(e.y, w1, fmaf(e.z, w2, fmaf(e.w, w3, acc[r]))));
        }
    }
}

// ---------------------------------------------------------------------------
// Main decoder: 1 block / batch row, 256 threads
// ---------------------------------------------------------------------------
__global__ __launch_bounds__(256, 1)
void decoder_main(const float* __restrict__ enc, const float* __restrict__ capc,
                  const float* __restrict__ demand, const float* __restrict__ Wk,
                  const float* __restrict__ Wv, float* __restrict__ out) {
    extern __shared__ __align__(16) float sm[];
    float* KT   = sm;              // 128*104 (K transposed [d][n])
    float* Kp2T = sm + 13312;      // 128*104 (Kp2 transposed [h][n])
    float* Vs   = sm + 26624;      // 101*128 (E during prologue, then V)
    float* comp = sm + 39552;      // 8*104
    float* redF = sm + 40384;      // 8*128
    float* redE = sm + 41408;      // 8*104
    __shared__ float red[256];
    __shared__ __align__(16) float vA[128];
    __shared__ __align__(16) float xin[132];
    __shared__ float logits[NP];
    __shared__ float dem_s[NP];
    __shared__ unsigned char maskA[NP], mask1A[NP];
    __shared__ float s_dyn, s_cap0, s_logp;
    __shared__ int s_idx, s_cnt;

    const int t = threadIdx.x, b = blockIdx.x;
    const int j = t & 127, half = t >> 7;
    const int w = t >> 5, lane = t & 31;

    // ---- load E (enc row-block) into Vs slot -----------------------------
    {
        const float4* eg = (const float4*)(enc + (size_t)b * Nq * 128);
        float4* e4 = (float4*)Vs;
        for (int i = t; i < Nq * 32; i += 256) e4[i] = eg[i];
    }
    __syncthreads();

    const int n0   = half ? 51 : 0;
    const int ncnt = half ? 50 : 51;
    const float4* E4 = (const float4*)Vs;
    float acc[17];

    // ---- K^T ----
    {
        const float* Wj = Wk + j; float* dst = KT + j * NP;
        for (int c0 = 0; c0 < ncnt; c0 += 17) {
            int cn = ncnt - c0; if (cn > 17) cn = 17;
            mm_chunk(E4, Wj, n0, c0, cn, acc);
            for (int r = 0; r < cn; r++) dst[n0 + c0 + r] = acc[r];
        }
    }
    // ---- Kp2^T = (E @ Wpk2)^T ----
    {
        const float* Wj = g_Wpk2 + j; float* dst = Kp2T + j * NP;
        for (int c0 = 0; c0 < ncnt; c0 += 17) {
            int cn = ncnt - c0; if (cn > 17) cn = 17;
            mm_chunk(E4, Wj, n0, c0, cn, acc);
            for (int r = 0; r < cn; r++) dst[n0 + c0 + r] = acc[r];
        }
    }
    // ---- V = E @ Wv, in-place over E (chunk-synced; both halves 3 chunks)
    {
        const float* Wj = Wv + j;
        for (int c0 = 0; c0 < 51; c0 += 17) {
            int cn = ncnt - c0; if (cn > 17) cn = 17;
            mm_chunk(E4, Wj, n0, c0, cn, acc);
            __syncthreads();
            for (int r = 0; r < cn; r++) Vs[(n0 + c0 + r) * 128 + j] = acc[r];
            __syncthreads();
        }
    }

    // ---- register slice of folded Wfw (129 x 128) ------------------------
    float wfw[64], wdyn;
#pragma unroll
    for (int k = 0; k < 64; k++) wfw[k] = g_Wfw[(half * 64 + k) * 128 + j];
    wdyn = half ? g_Wfw[128 * 128 + j] : 0.f;

    // ---- initial state ----------------------------------------------------
    if (t == 0) {
        s_cap0 = capc[0]; s_dyn = capc[b]; s_logp = 0.f; s_cnt = 0;
        xin[128] = capc[b];
    }
    if (t < NP) dem_s[t] = (t < Nq) ? demand[b * Nq + t] : 1e30f;
    if (t < 128) xin[t] = enc[(size_t)b * Nq * 128 + t];
    __syncthreads();
    if (t < NP) {
        mask1A[t] = (t == 0 || t >= Nq) ? 1 : 0;
        maskA[t]  = (t == 0 || t >= Nq || dem_s[t] > s_dyn) ? 1 : 0;
    }
    __syncthreads();

    const float4* KT4   = (const float4*)KT;
    const float4* Kp2T4 = (const float4*)Kp2T;
    const float4* Vs4   = (const float4*)Vs;
    const float4* vA4   = (const float4*)vA;
    float4* comp4 = (float4*)comp;
    float4* redE4 = (float4*)redE;
    float4* redF4 = (float4*)redF;

    // =========================== step loop =================================
    for (int step = 0; step < Tq; step++) {
        // ---- Q = [xin,dyn] @ Wfw + poolW   (x0.25 folded for compat) -----
        {
            const float4* x4 = (const float4*)xin;
            float a = 0.f;
#pragma unroll
            for (int k4 = 0; k4 < 16; k4++) {
                float4 x = x4[half * 16 + k4];
                a += x.x * wfw[4*k4] + x.y * wfw[4*k4+1] + x.z * wfw[4*k4+2] + x.w * wfw[4*k4+3];
            }
            a += xin[128] * wdyn;     // wdyn==0 for half 0
            red[t] = a;
        }
        __syncthreads();
        if (t < 128)
            vA[t] = (red[t] + red[t + 128] + g_poolW[((size_t)b * Tq + step) * 128 + t]) * 0.25f;
        __syncthreads();

        // ---- compat: warp w = head w; lane covers 4 n via float4 ---------
        if (lane < NP4) {
            float4 a4 = make_float4(0.f, 0.f, 0.f, 0.f);
#pragma unroll
            for (int d4 = 0; d4 < 4; d4++) {
                float4 q = vA4[w * 4 + d4];
                float4 k0 = KT4[(w * 16 + d4 * 4 + 0) * NP4 + lane];
                float4 k1 = KT4[(w * 16 + d4 * 4 + 1) * NP4 + lane];
                float4 k2 = KT4[(w * 16 + d4 * 4 + 2) * NP4 + lane];
                float4 k3 = KT4[(w * 16 + d4 * 4 + 3) * NP4 + lane];
                a4.x += q.x*k0.x + q.y*k1.x + q.z*k2.x + q.w*k3.x;
                a4.y += q.x*k0.y + q.y*k1.y + q.z*k2.y + q.w*k3.y;
                a4.z += q.x*k0.z + q.y*k1.z + q.z*k2.z + q.w*k3.z;
                a4.w += q.x*k0.w + q.y*k1.w + q.z*k2.w + q.w*k3.w;
            }
            comp4[w * NP4 + lane] = a4;
        }
        __syncthreads();

        // ---- masked softmax per head (warp w) ----------------------------
        {
            const int nA = lane, nB = lane + 32, nC = lane + 64, nD = lane + 96;
            float v0 = maskA[nA] ? -INFINITY : comp[w * NP + nA];
            float v1 = maskA[nB] ? -INFINITY : comp[w * NP + nB];
            float v2 = maskA[nC] ? -INFINITY : comp[w * NP + nC];
            float v3 = (nD < NP && !maskA[nD]) ? comp[w * NP + nD] : -INFINITY;
            float mx = fmaxf(fmaxf(v0, v1), fmaxf(v2, v3));
#pragma unroll
            for (int o = 16; o; o >>= 1) mx = fmaxf(mx, __shfl_xor_sync(0xffffffffu, mx, o));
            float e0 = (v0 == -INFINITY) ? 0.f : expf(v0 - mx);
            float e1 = (v1 == -INFINITY) ? 0.f : expf(v1 - mx);
            float e2 = (v2 == -INFINITY) ? 0.f : expf(v2 - mx);
            float e3 = (v3 == -INFINITY) ? 0.f : expf(v3 - mx);
            float s = e0 + e1 + e2 + e3;
#pragma unroll
            for (int o = 16; o; o >>= 1) s += __shfl_xor_sync(0xffffffffu, s, o);
            float inv = 1.f / s;
            comp[w * NP + nA] = e0 * inv;
            comp[w * NP + nB] = e1 * inv;
            comp[w * NP + nC] = e2 * inv;
            if (nD < NP) comp[w * NP + nD] = e3 * inv;
        }
        __syncthreads();

        // ---- glimpse partials: thread (g=o-group, ns=n-slice) ------------
        {
            const int g = lane, ns = w;
            const int h = g >> 2;
            const int nn0 = ns * 13;
            const int cnt = (ns == 7) ? 10 : 13;
            float4 a4 = make_float4(0.f, 0.f, 0.f, 0.f);
            for (int r = 0; r < cnt; r++) {
                int n = nn0 + r;
                float sc = comp[h * NP + n];
                float4 v = Vs4[n * 32 + g];
                a4.x += sc * v.x; a4.y += sc * v.y; a4.z += sc * v.z; a4.w += sc * v.w;
            }
            redF4[ns * 32 + g] = a4;
        }
        __syncthreads();
        if (t < 128) {
            float s = redF[t];
#pragma unroll
            for (int k = 1; k < 8; k++) s += redF[k * 128 + t];
            vA[t] = s;                       // glimpse_pre (unscaled)
        }
        __syncthreads();

        // ---- logits partials: warp w covers dims [w*16, w*16+16) ---------
        if (lane < NP4) {
            float4 a4 = make_float4(0.f, 0.f, 0.f, 0.f);
#pragma unroll
            for (int d4 = 0; d4 < 4; d4++) {
                float4 q = vA4[w * 4 + d4];
                float4 k0 = Kp2T4[(w * 16 + d4 * 4 + 0) * NP4 + lane];
                float4 k1 = Kp2T4[(w * 16 + d4 * 4 + 1) * NP4 + lane];
                float4 k2 = Kp2T4[(w * 16 + d4 * 4 + 2) * NP4 + lane];
                float4 k3 = Kp2T4[(w * 16 + d4 * 4 + 3) * NP4 + lane];
                a4.x += q.x*k0.x + q.y*k1.x + q.z*k2.x + q.w*k3.x;
                a4.y += q.x*k0.y + q.y*k1.y + q.z*k2.y + q.w*k3.y;
                a4.z += q.x*k0.z + q.y*k1.z + q.z*k2.z + q.w*k3.z;
                a4.w += q.x*k0.w + q.y*k1.w + q.z*k2.w + q.w*k3.w;
            }
            redE4[w * NP4 + lane] = a4;
        }
        __syncthreads();
        if (t < NP) {
            float s = redE[t];
#pragma unroll
            for (int k = 1; k < 8; k++) s += redE[k * NP + t];
            float c2 = s * 0.08838834764831845f;
            logits[t] = maskA[t] ? -INFINITY : 10.f * tanhf(c2);
        }
        __syncthreads();

        // ---- argmax + log-softmax + state update (warp 0) ----------------
        if (t < 32) {
            float bv = -INFINITY; int bi = NP;
            for (int n = t; n < NP; n += 32) {
                float v = logits[n];
                if (v > bv || (v == bv && n < bi)) { bv = v; bi = n; }
            }
#pragma unroll
            for (int o = 16; o; o >>= 1) {
                float ov = __shfl_xor_sync(0xffffffffu, bv, o);
                int   oi = __shfl_xor_sync(0xffffffffu, bi, o);
                if (ov > bv || (ov == bv && oi < bi)) { bv = ov; bi = oi; }
            }
            float s = 0.f;
            for (int n = t; n < NP; n += 32) {
                float v = logits[n];
                s += (v == -INFINITY) ? 0.f : expf(v - bv);
            }
#pragma unroll
            for (int o = 16; o; o >>= 1) s += __shfl_xor_sync(0xffffffffu, s, o);

            if (t == 0) {
                if (s_cnt < Nq - 1) s_logp += -logf(s);
                s_idx = bi;
                out[b * Tq + step] = (float)bi;
                float nd = (bi == 0) ? s_cap0 : (s_dyn - dem_s[bi]);
                s_dyn = nd;
                xin[128] = nd;
                if (bi > 0 && !mask1A[bi]) { mask1A[bi] = 1; s_cnt++; }
                mask1A[0] = (bi == 0) ? 1 : 0;
            }
        }
        __syncthreads();
        if (t < NP)
            maskA[t] = (mask1A[t] || dem_s[t] > s_dyn) ? 1 : 0;
        __syncthreads();
        if (t < 32) {
            int open = 0;
            for (int n = t; n < NP; n += 32) open |= (maskA[n] == 0);
            open = __any_sync(0xffffffffu, open);
            if (t == 0 && !open) maskA[0] = 0;
        }
        if (t < 128) xin[t] = enc[((size_t)b * Nq + s_idx) * 128 + t];
        __syncthreads();
    }

    if (t == 0) out[Bq * Tq + b] = s_logp;
}

// ---------------------------------------------------------------------------
extern "C" void kernel_launch(void* const* d_in, const int* in_sizes, int n_in,
                              void* d_out, int out_size) {
    const float *enc = nullptr, *pool = nullptr, *capc = nullptr, *dem = nullptr, *Wfc = nullptr;
    const float* w16[8] = {nullptr};
    int nw = 0;
    for (int i = 0; i < n_in; i++) {
        int s = in_sizes[i];
        if      (s == Bq * Nq * 128) enc  = (const float*)d_in[i];
        else if (s == Bq * Hq)       pool = (const float*)d_in[i];
        else if (s == Bq)            capc = (const float*)d_in[i];
        else if (s == Bq * Nq)       dem  = (const float*)d_in[i];
        else if (s == (Hq + 1) * Hq) Wfc  = (const float*)d_in[i];
        else if (s == Hq * Hq) { if (nw < 8) w16[nw++] = (const float*)d_in[i]; }
    }
    // dict order among 128x128: W_fc1, W_w, W_k, W_v, W_attnfc, W_pk
    const float* Wfc1 = w16[0];
    const float* Ww   = w16[1];
    const float* Wk   = w16[2];
    const float* Wv   = w16[3];
    const float* Wat  = w16[4];
    const float* Wpk  = w16[5];

    const int smem_main = 42240 * (int)sizeof(float);   // 168960 B
    cudaFuncSetAttribute(decoder_main, cudaFuncAttributeMaxDynamicSharedMemorySize, smem_main);

    precomp0<<<257, 128>>>(Wfc, Ww, Wat, Wpk);
    precomp2<<<Bq / 2, 256>>>(pool, Wfc1, Ww);
    decoder_main<<<Bq, 256, smem_main>>>(enc, capc, dem, Wk, Wv, (float*)d_out);
}

// round 6
// speedup vs baseline: 4.1065x; 1.3455x over previous
#include <cuda_runtime.h>
#include <cuda_bf16.h>
#include <math.h>

#define Bq 512
#define Nq 101
#define Hq 128
#define Tq 140
#define NP 104
#define NPC 108   // comp/redE row stride (conflict-free for h-strided reads)

// __device__ scratch
__device__ float g_Wfw [129 * 128];                 // Wfc @ Ww
__device__ float g_Wpk2[128 * 128];                 // Wpk @ Wat^T   [k][o]
__device__ float g_poolW[(size_t)Bq * Tq * 128];    // pool@Wfc1^(s+1)@Ww  [b][s][:]
__device__ float g_G[(size_t)Bq * Nq * 128];        // enc@Wfw[:128]       [b][n][:]

// ---------------------------------------------------------------------------
// P0: fold weights
// ---------------------------------------------------------------------------
__global__ void precomp0(const float* __restrict__ Wfc, const float* __restrict__ Ww,
                         const float* __restrict__ Wat, const float* __restrict__ Wpk) {
    __shared__ __align__(16) float row[128];
    const int t = threadIdx.x, bidx = blockIdx.x;
    if (bidx < 129) {
        row[t] = Wfc[bidx * 128 + t];
        __syncthreads();
        const float4* r4 = (const float4*)row;
        float a = 0.f;
        for (int k4 = 0; k4 < 32; k4++) {
            float4 r = r4[k4];
            a += r.x * Ww[(4 * k4 + 0) * 128 + t] + r.y * Ww[(4 * k4 + 1) * 128 + t]
               + r.z * Ww[(4 * k4 + 2) * 128 + t] + r.w * Ww[(4 * k4 + 3) * 128 + t];
        }
        g_Wfw[bidx * 128 + t] = a;
    } else {
        const int d = bidx - 129;
        row[t] = Wpk[d * 128 + t];
        __syncthreads();
        const float4* r4 = (const float4*)row;
        const float4* w4 = (const float4*)(Wat + t * 128);
        float a = 0.f;
        for (int k4 = 0; k4 < 32; k4++) {
            float4 r = r4[k4]; float4 wv = w4[k4];
            a += r.x * wv.x + r.y * wv.y + r.z * wv.z + r.w * wv.w;
        }
        g_Wpk2[d * 128 + t] = a;
    }
}

// ---------------------------------------------------------------------------
// P2: pool chain folded through Ww. 2 batches/block.
// ---------------------------------------------------------------------------
__global__ __launch_bounds__(256)
void precomp2(const float* __restrict__ pool, const float* __restrict__ Wfc1,
              const float* __restrict__ Ww) {
    __shared__ __align__(16) float pA[128], pB[128];
    __shared__ float red2[256], red3[256];
    const int t = threadIdx.x, j = t & 127, kh = t >> 7;
    const int b0 = blockIdx.x * 2;
    float wf[64], wq[64];
#pragma unroll
    for (int k = 0; k < 64; k++) {
        wf[k] = Wfc1[(kh * 64 + k) * 128 + j];
        wq[k] = Ww  [(kh * 64 + k) * 128 + j];
    }
    if (t < 128) { pA[t] = pool[b0 * 128 + t]; pB[t] = pool[(b0 + 1) * 128 + t]; }
    __syncthreads();
    for (int s = 0; s < Tq; s++) {
        const float4* pa4 = (const float4*)pA; const float4* pb4 = (const float4*)pB;
        float a0 = 0.f, a1 = 0.f;
#pragma unroll
        for (int k4 = 0; k4 < 16; k4++) {
            float4 xa = pa4[kh * 16 + k4], xb = pb4[kh * 16 + k4];
            a0 += xa.x * wf[4*k4] + xa.y * wf[4*k4+1] + xa.z * wf[4*k4+2] + xa.w * wf[4*k4+3];
            a1 += xb.x * wf[4*k4] + xb.y * wf[4*k4+1] + xb.z * wf[4*k4+2] + xb.w * wf[4*k4+3];
        }
        red2[t] = a0; red3[t] = a1;
        __syncthreads();
        if (t < 128) { pA[t] = red2[t] + red2[t + 128]; pB[t] = red3[t] + red3[t + 128]; }
        __syncthreads();
        a0 = 0.f; a1 = 0.f;
#pragma unroll
        for (int k4 = 0; k4 < 16; k4++) {
            float4 xa = pa4[kh * 16 + k4], xb = pb4[kh * 16 + k4];
            a0 += xa.x * wq[4*k4] + xa.y * wq[4*k4+1] + xa.z * wq[4*k4+2] + xa.w * wq[4*k4+3];
            a1 += xb.x * wq[4*k4] + xb.y * wq[4*k4+1] + xb.z * wq[4*k4+2] + xb.w * wq[4*k4+3];
        }
        red2[t] = a0; red3[t] = a1;
        __syncthreads();
        if (t < 128) {
            g_poolW[((size_t)b0 * Tq + s) * 128 + t]       = red2[t] + red2[t + 128];
            g_poolW[((size_t)(b0 + 1) * Tq + s) * 128 + t] = red3[t] + red3[t + 128];
        }
        __syncthreads();
    }
}

// ---------------------------------------------------------------------------
// prologue matmul: 13-row chunk of one output column; E from global (bcast)
// ---------------------------------------------------------------------------
__device__ __forceinline__ void mm13(const float4* __restrict__ E4,
                                     const float* __restrict__ Wj,
                                     int n0, int cn, float* acc) {
#pragma unroll
    for (int r = 0; r < 13; r++) acc[r] = 0.f;
#pragma unroll 2
    for (int d4 = 0; d4 < 32; d4++) {
        float w0 = Wj[(4 * d4 + 0) * 128], w1 = Wj[(4 * d4 + 1) * 128];
        float w2 = Wj[(4 * d4 + 2) * 128], w3 = Wj[(4 * d4 + 3) * 128];
#pragma unroll
        for (int r = 0; r < 13; r++) if (r < cn) {
            float4 e = E4[(n0 + r) * 32 + d4];
            acc[r] = fmaf(e.x, w0, fmaf(e.y, w1, fmaf(e.z, w2, fmaf(e.w, w3, acc[r]))));
        }
    }
}

// ---------------------------------------------------------------------------
// Main decoder: 1 block / batch row, 256 threads, 2 CTAs/SM
// ---------------------------------------------------------------------------
__global__ __launch_bounds__(256, 2)
void decoder_main(const float* __restrict__ enc, const float* __restrict__ capc,
                  const float* __restrict__ demand, const float* __restrict__ Wk,
                  const float* __restrict__ Wv, float* __restrict__ out) {
    extern __shared__ __align__(16) float sm[];
    float* KT   = sm;            // 128*104   (K^T [d][n]); also staging for V / Kp2
    float* comp = sm + 13312;    // 8*108
    float* redE = sm + 14176;    // 8*108
    float* redF = sm + 15040;    // 8*128
    __shared__ __align__(16) float vA[128];
    __shared__ float logits[NP];
    __shared__ float dem_s[NP];
    __shared__ __align__(4) unsigned char maskA[NP], mask1A[NP];
    __shared__ float s_dyn, s_cap0, s_logp;
    __shared__ int s_idx, s_cnt;

    const int t = threadIdx.x, b = blockIdx.x;
    const int j = t & 127, half = t >> 7;
    const int w = t >> 5, lane = t & 31;

    const float4* E4 = (const float4*)(enc + (size_t)b * Nq * 128);
    const int nbase = half ? 51 : 0;
    const int ncnt  = half ? 50 : 51;
    float acc[13];

    // ---- Phase V: Vtmp[n][o] into KT area ---------------------------------
    for (int c0 = 0; c0 < ncnt; c0 += 13) {
        int cn = ncnt - c0; if (cn > 13) cn = 13;
        mm13(E4, Wv + j, nbase + c0, cn, acc);
        for (int r = 0; r < cn; r++) KT[(nbase + c0 + r) * 128 + j] = acc[r];
    }
    __syncthreads();
    // pickup V slices: thread (w,lane) holds V[n][4lane..] for n = w*13+r
    float4 vr4[13];
    {
        const float4* Vt4 = (const float4*)KT;
        const int vcnt = (w == 7) ? 10 : 13;
#pragma unroll
        for (int r = 0; r < 13; r++)
            vr4[r] = (r < vcnt) ? Vt4[(w * 13 + r) * 32 + lane]
                                : make_float4(0.f, 0.f, 0.f, 0.f);
    }
    __syncthreads();

    // ---- Phase Kp2: Kp2T[d][n] into KT area -------------------------------
    for (int c0 = 0; c0 < ncnt; c0 += 13) {
        int cn = ncnt - c0; if (cn > 13) cn = 13;
        mm13(E4, g_Wpk2 + j, nbase + c0, cn, acc);
        for (int r = 0; r < cn; r++) KT[j * NP + (nbase + c0 + r)] = acc[r];
    }
    if (t < 128) { KT[t * NP + 101] = 0.f; KT[t * NP + 102] = 0.f; KT[t * NP + 103] = 0.f; }
    __syncthreads();
    // pickup Kp2 slices: thread (w,lane<26) holds rows 16w..16w+15, n=4lane..
    float4 kp2r4[16];
    {
        const float4* K4 = (const float4*)KT;
        if (lane < 26) {
#pragma unroll
            for (int r = 0; r < 16; r++) kp2r4[r] = K4[(w * 16 + r) * 26 + lane];
        } else {
#pragma unroll
            for (int r = 0; r < 16; r++) kp2r4[r] = make_float4(0.f, 0.f, 0.f, 0.f);
        }
    }
    __syncthreads();

    // ---- Phase K: K^T[d][n] into KT area (final resident) -----------------
    for (int c0 = 0; c0 < ncnt; c0 += 13) {
        int cn = ncnt - c0; if (cn > 13) cn = 13;
        mm13(E4, Wk + j, nbase + c0, cn, acc);
        for (int r = 0; r < cn; r++) KT[j * NP + (nbase + c0 + r)] = acc[r];
    }
    if (t < 128) { KT[t * NP + 101] = 0.f; KT[t * NP + 102] = 0.f; KT[t * NP + 103] = 0.f; }

    // ---- Phase G: g_G[b][n][:] = E @ Wfw[:128] ----------------------------
    {
        float* gout = g_G + (size_t)b * Nq * 128;
        for (int c0 = 0; c0 < ncnt; c0 += 13) {
            int cn = ncnt - c0; if (cn > 13) cn = 13;
            mm13(E4, g_Wfw + j, nbase + c0, cn, acc);
            for (int r = 0; r < cn; r++) gout[(size_t)(nbase + c0 + r) * 128 + j] = acc[r];
        }
    }

    // ---- init state -------------------------------------------------------
    float wdyn = (t < 128) ? g_Wfw[128 * 128 + t] : 0.f;
    if (t == 0) {
        s_cap0 = capc[0]; s_dyn = capc[b]; s_logp = 0.f; s_cnt = 0; s_idx = 0;
    }
    if (t < NP) dem_s[t] = (t < Nq) ? demand[b * Nq + t] : 1e30f;
    __syncthreads();
    if (t < NP) {
        mask1A[t] = (t == 0 || t >= Nq) ? 1 : 0;
        maskA[t]  = (t == 0 || t >= Nq || dem_s[t] > s_dyn) ? 1 : 0;
    }
    __syncthreads();

    const float4* KT4 = (const float4*)KT;
    const float4* vA4 = (const float4*)vA;
    float4* comp4 = (float4*)comp;
    float4* redE4 = (float4*)redE;
    float4* redF4 = (float4*)redF;
    const float* gG  = g_G + (size_t)b * Nq * 128;
    const float* gPW = g_poolW + (size_t)b * Tq * 128;

    float pw = (t < 128) ? gPW[t] : 0.f;

    // =========================== step loop =================================
    for (int step = 0; step < Tq; step++) {
        // ---- Q(scaled) = (G[idx] + dyn*wdyn + poolW) * 0.25 ---------------
        if (t < 128) {
            float gq = gG[(size_t)s_idx * 128 + t];
            vA[t] = (gq + s_dyn * wdyn + pw) * 0.25f;
            if (step + 1 < Tq) pw = gPW[(size_t)(step + 1) * 128 + t]; // prefetch
        }
        __syncthreads();                                              // bar1

        // ---- compat + in-warp masked softmax (warp w = head w) -----------
        {
            float4 a4 = make_float4(0.f, 0.f, 0.f, 0.f);
            if (lane < 26) {
#pragma unroll
                for (int d4 = 0; d4 < 4; d4++) {
                    float4 q = vA4[w * 4 + d4];
                    float4 k0 = KT4[(w * 16 + d4 * 4 + 0) * 26 + lane];
                    float4 k1 = KT4[(w * 16 + d4 * 4 + 1) * 26 + lane];
                    float4 k2 = KT4[(w * 16 + d4 * 4 + 2) * 26 + lane];
                    float4 k3 = KT4[(w * 16 + d4 * 4 + 3) * 26 + lane];
                    a4.x += q.x*k0.x + q.y*k1.x + q.z*k2.x + q.w*k3.x;
                    a4.y += q.x*k0.y + q.y*k1.y + q.z*k2.y + q.w*k3.y;
                    a4.z += q.x*k0.z + q.y*k1.z + q.z*k2.z + q.w*k3.z;
                    a4.w += q.x*k0.w + q.y*k1.w + q.z*k2.w + q.w*k3.w;
                }
            }
            uchar4 m4 = make_uchar4(1, 1, 1, 1);
            if (lane < 26) m4 = *(const uchar4*)(maskA + 4 * lane);
            float v0 = m4.x ? -INFINITY : a4.x;
            float v1 = m4.y ? -INFINITY : a4.y;
            float v2 = m4.z ? -INFINITY : a4.z;
            float v3 = m4.w ? -INFINITY : a4.w;
            float mx = fmaxf(fmaxf(v0, v1), fmaxf(v2, v3));
#pragma unroll
            for (int o = 16; o; o >>= 1) mx = fmaxf(mx, __shfl_xor_sync(0xffffffffu, mx, o));
            float e0 = (v0 == -INFINITY) ? 0.f : expf(v0 - mx);
            float e1 = (v1 == -INFINITY) ? 0.f : expf(v1 - mx);
            float e2 = (v2 == -INFINITY) ? 0.f : expf(v2 - mx);
            float e3 = (v3 == -INFINITY) ? 0.f : expf(v3 - mx);
            float s = e0 + e1 + e2 + e3;
#pragma unroll
            for (int o = 16; o; o >>= 1) s += __shfl_xor_sync(0xffffffffu, s, o);
            float inv = 1.f / s;
            if (lane < 26)
                comp4[w * 27 + lane] = make_float4(e0 * inv, e1 * inv, e2 * inv, e3 * inv);
        }
        __syncthreads();                                              // bar2

        // ---- glimpse partials: thread (ns=w, g=lane), V in regs ----------
        {
            const int h = lane >> 2;
            const int nb = w * 13;
            const int cnt = (w == 7) ? 10 : 13;
            const float* cr = comp + h * NPC + nb;
            float4 a4 = make_float4(0.f, 0.f, 0.f, 0.f);
#pragma unroll
            for (int r = 0; r < 13; r++) if (r < cnt) {
                float sc = cr[r];
                float4 v = vr4[r];
                a4.x += sc * v.x; a4.y += sc * v.y; a4.z += sc * v.z; a4.w += sc * v.w;
            }
            redF4[w * 32 + lane] = a4;
        }
        __syncthreads();                                              // bar3
        if (t < 128) {
            float s = redF[t];
#pragma unroll
            for (int k = 1; k < 8; k++) s += redF[k * 128 + t];
            vA[t] = s;                       // glimpse_pre
        }
        __syncthreads();                                              // bar4

        // ---- logits partials: Kp2 in regs, vA broadcast ------------------
        if (lane < 26) {
            float4 a4 = make_float4(0.f, 0.f, 0.f, 0.f);
#pragma unroll
            for (int d4 = 0; d4 < 4; d4++) {
                float4 q = vA4[w * 4 + d4];
                float4 k0 = kp2r4[d4 * 4 + 0];
                float4 k1 = kp2r4[d4 * 4 + 1];
                float4 k2 = kp2r4[d4 * 4 + 2];
                float4 k3 = kp2r4[d4 * 4 + 3];
                a4.x += q.x*k0.x + q.y*k1.x + q.z*k2.x + q.w*k3.x;
                a4.y += q.x*k0.y + q.y*k1.y + q.z*k2.y + q.w*k3.y;
                a4.z += q.x*k0.z + q.y*k1.z + q.z*k2.z + q.w*k3.z;
                a4.w += q.x*k0.w + q.y*k1.w + q.z*k2.w + q.w*k3.w;
            }
            redE4[w * 27 + lane] = a4;
        }
        __syncthreads();                                              // bar5
        if (t < NP) {
            float s = redE[t];
#pragma unroll
            for (int k = 1; k < 8; k++) s += redE[k * NPC + t];
            float c2 = s * 0.08838834764831845f;
            logits[t] = maskA[t] ? -INFINITY : 10.f * tanhf(c2);
        }
        __syncthreads();                                              // bar6

        // ---- argmax + lse + state + mask update (warp 0) -----------------
        if (t < 32) {
            float bv = -INFINITY; int bi = NP;
#pragma unroll
            for (int k = 0; k < 4; k++) {
                int n = t + 32 * k;
                if (n < NP) {
                    float v = logits[n];
                    if (v > bv || (v == bv && n < bi)) { bv = v; bi = n; }
                }
            }
#pragma unroll
            for (int o = 16; o; o >>= 1) {
                float ov = __shfl_xor_sync(0xffffffffu, bv, o);
                int   oi = __shfl_xor_sync(0xffffffffu, bi, o);
                if (ov > bv || (ov == bv && oi < bi)) { bv = ov; bi = oi; }
            }
            float s = 0.f;
#pragma unroll
            for (int k = 0; k < 4; k++) {
                int n = t + 32 * k;
                if (n < NP) {
                    float v = logits[n];
                    s += (v == -INFINITY) ? 0.f : expf(v - bv);
                }
            }
#pragma unroll
            for (int o = 16; o; o >>= 1) s += __shfl_xor_sync(0xffffffffu, s, o);

            float nd = (bi == 0) ? s_cap0 : (s_dyn - dem_s[bi]);
            if (t == 0) {
                if (s_cnt < Nq - 1) s_logp += -logf(s);
                out[b * Tq + step] = (float)bi;
                s_idx = bi; s_dyn = nd;
                mask1A[0] = (bi == 0) ? 1 : 0;
            }
            __syncwarp();
            if (bi > 0 && t == (bi & 31)) {
                if (!mask1A[bi]) { mask1A[bi] = 1; s_cnt++; }
            }
            __syncwarp();
            int open = 0;
#pragma unroll
            for (int k = 0; k < 4; k++) {
                int n = t + 32 * k;
                if (n < NP) {
                    int m = (mask1A[n] || dem_s[n] > nd) ? 1 : 0;
                    maskA[n] = (unsigned char)m;
                    open |= (!m);
                }
            }
            unsigned bal = __ballot_sync(0xffffffffu, open);
            if (t == 0 && bal == 0) maskA[0] = 0;
        }
        __syncthreads();                                              // bar7
    }

    if (t == 0) out[Bq * Tq + b] = s_logp;
}

// ---------------------------------------------------------------------------
extern "C" void kernel_launch(void* const* d_in, const int* in_sizes, int n_in,
                              void* d_out, int out_size) {
    const float *enc = nullptr, *pool = nullptr, *capc = nullptr, *dem = nullptr, *Wfc = nullptr;
    const float* w16[8] = {nullptr};
    int nw = 0;
    for (int i = 0; i < n_in; i++) {
        int s = in_sizes[i];
        if      (s == Bq * Nq * 128) enc  = (const float*)d_in[i];
        else if (s == Bq * Hq)       pool = (const float*)d_in[i];
        else if (s == Bq)            capc = (const float*)d_in[i];
        else if (s == Bq * Nq)       dem  = (const float*)d_in[i];
        else if (s == (Hq + 1) * Hq) Wfc  = (const float*)d_in[i];
        else if (s == Hq * Hq) { if (nw < 8) w16[nw++] = (const float*)d_in[i]; }
    }
    // dict order among 128x128: W_fc1, W_w, W_k, W_v, W_attnfc, W_pk
    const float* Wfc1 = w16[0];
    const float* Ww   = w16[1];
    const float* Wk   = w16[2];
    const float* Wv   = w16[3];
    const float* Wat  = w16[4];
    const float* Wpk  = w16[5];

    const int smem_main = 16064 * (int)sizeof(float);   // 64256 B dynamic
    cudaFuncSetAttribute(decoder_main, cudaFuncAttributeMaxDynamicSharedMemorySize, smem_main);

    precomp0<<<257, 128>>>(Wfc, Ww, Wat, Wpk);
    precomp2<<<Bq / 2, 256>>>(pool, Wfc1, Ww);
    decoder_main<<<Bq, 256, smem_main>>>(enc, capc, dem, Wk, Wv, (float*)d_out);
}

// round 7
// speedup vs baseline: 4.1687x; 1.0152x over previous
#include <cuda_runtime.h>
#include <cuda_bf16.h>
#include <math.h>

#define Bq 512
#define Nq 101
#define Hq 128
#define Tq 140
#define NP 104
#define NPC 108

// __device__ scratch
__device__ float g_Wfw [129 * 128];                 // Wfc @ Ww
__device__ float g_Wpk2[128 * 128];                 // Wpk @ Wat^T   [k][o]
__device__ float g_poolW[(size_t)Bq * Tq * 128];    // pool@Wfc1^(s+1)@Ww  [b][s][:]
__device__ float g_G[(size_t)Bq * Nq * 128];        // enc@Wfw[:128]       [b][n][:]

// ---------------------------------------------------------------------------
// P0: fold weights
// ---------------------------------------------------------------------------
__global__ void precomp0(const float* __restrict__ Wfc, const float* __restrict__ Ww,
                         const float* __restrict__ Wat, const float* __restrict__ Wpk) {
    __shared__ __align__(16) float row[128];
    const int t = threadIdx.x, bidx = blockIdx.x;
    if (bidx < 129) {
        row[t] = Wfc[bidx * 128 + t];
        __syncthreads();
        const float4* r4 = (const float4*)row;
        float a = 0.f;
        for (int k4 = 0; k4 < 32; k4++) {
            float4 r = r4[k4];
            a += r.x * Ww[(4 * k4 + 0) * 128 + t] + r.y * Ww[(4 * k4 + 1) * 128 + t]
               + r.z * Ww[(4 * k4 + 2) * 128 + t] + r.w * Ww[(4 * k4 + 3) * 128 + t];
        }
        g_Wfw[bidx * 128 + t] = a;
    } else {
        const int d = bidx - 129;
        row[t] = Wpk[d * 128 + t];
        __syncthreads();
        const float4* r4 = (const float4*)row;
        const float4* w4 = (const float4*)(Wat + t * 128);
        float a = 0.f;
        for (int k4 = 0; k4 < 32; k4++) {
            float4 r = r4[k4]; float4 wv = w4[k4];
            a += r.x * wv.x + r.y * wv.y + r.z * wv.z + r.w * wv.w;
        }
        g_Wpk2[d * 128 + t] = a;
    }
}

// ---------------------------------------------------------------------------
// P2: pool chain folded through Ww. 2 batches/block.
// ---------------------------------------------------------------------------
__global__ __launch_bounds__(256)
void precomp2(const float* __restrict__ pool, const float* __restrict__ Wfc1,
              const float* __restrict__ Ww) {
    __shared__ __align__(16) float pA[128], pB[128];
    __shared__ float red2[256], red3[256];
    const int t = threadIdx.x, j = t & 127, kh = t >> 7;
    const int b0 = blockIdx.x * 2;
    float wf[64], wq[64];
#pragma unroll
    for (int k = 0; k < 64; k++) {
        wf[k] = Wfc1[(kh * 64 + k) * 128 + j];
        wq[k] = Ww  [(kh * 64 + k) * 128 + j];
    }
    if (t < 128) { pA[t] = pool[b0 * 128 + t]; pB[t] = pool[(b0 + 1) * 128 + t]; }
    __syncthreads();
    for (int s = 0; s < Tq; s++) {
        const float4* pa4 = (const float4*)pA; const float4* pb4 = (const float4*)pB;
        float a0 = 0.f, a1 = 0.f;
#pragma unroll
        for (int k4 = 0; k4 < 16; k4++) {
            float4 xa = pa4[kh * 16 + k4], xb = pb4[kh * 16 + k4];
            a0 += xa.x * wf[4*k4] + xa.y * wf[4*k4+1] + xa.z * wf[4*k4+2] + xa.w * wf[4*k4+3];
            a1 += xb.x * wf[4*k4] + xb.y * wf[4*k4+1] + xb.z * wf[4*k4+2] + xb.w * wf[4*k4+3];
        }
        red2[t] = a0; red3[t] = a1;
        __syncthreads();
        if (t < 128) { pA[t] = red2[t] + red2[t + 128]; pB[t] = red3[t] + red3[t + 128]; }
        __syncthreads();
        a0 = 0.f; a1 = 0.f;
#pragma unroll
        for (int k4 = 0; k4 < 16; k4++) {
            float4 xa = pa4[kh * 16 + k4], xb = pb4[kh * 16 + k4];
            a0 += xa.x * wq[4*k4] + xa.y * wq[4*k4+1] + xa.z * wq[4*k4+2] + xa.w * wq[4*k4+3];
            a1 += xb.x * wq[4*k4] + xb.y * wq[4*k4+1] + xb.z * wq[4*k4+2] + xb.w * wq[4*k4+3];
        }
        red2[t] = a0; red3[t] = a1;
        __syncthreads();
        if (t < 128) {
            g_poolW[((size_t)b0 * Tq + s) * 128 + t]       = red2[t] + red2[t + 128];
            g_poolW[((size_t)(b0 + 1) * Tq + s) * 128 + t] = red3[t] + red3[t + 128];
        }
        __syncthreads();
    }
}

// ---------------------------------------------------------------------------
// prologue matmul: 13-row chunk of one output column; E from global (bcast)
// ---------------------------------------------------------------------------
__device__ __forceinline__ void mm13(const float4* __restrict__ E4,
                                     const float* __restrict__ Wj,
                                     int n0, int cn, float* acc) {
#pragma unroll
    for (int r = 0; r < 13; r++) acc[r] = 0.f;
#pragma unroll 2
    for (int d4 = 0; d4 < 32; d4++) {
        float w0 = Wj[(4 * d4 + 0) * 128], w1 = Wj[(4 * d4 + 1) * 128];
        float w2 = Wj[(4 * d4 + 2) * 128], w3 = Wj[(4 * d4 + 3) * 128];
#pragma unroll
        for (int r = 0; r < 13; r++) if (r < cn) {
            float4 e = E4[(n0 + r) * 32 + d4];
            acc[r] = fmaf(e.x, w0, fmaf(e.y, w1, fmaf(e.z, w2, fmaf(e.w, w3, acc[r]))));
        }
    }
}

// ---------------------------------------------------------------------------
// Main decoder: 1 block / batch row, 256 threads, 2 CTAs/SM.
// Per-step cross-warp sync reduced to 3 block barriers.
// ---------------------------------------------------------------------------
__global__ __launch_bounds__(256, 2)
void decoder_main(const float* __restrict__ enc, const float* __restrict__ capc,
                  const float* __restrict__ demand, const float* __restrict__ Wk,
                  const float* __restrict__ Wv, float* __restrict__ out) {
    extern __shared__ __align__(16) float sm[];
    float* KT   = sm;            // 128*104  (K^T [d][n]); staging for V/Kp2 in prologue
    float* comp = sm + 13312;    // 8 * 27 float4 (warp-private softmax rows)
    float* redE = sm + 14176;    // 8 * 27 float4
    __shared__ __align__(16) float vA[128];
    __shared__ float logits[NP];
    __shared__ float dem_s[NP];
    __shared__ __align__(4) unsigned char maskA[NP], mask1A[NP];
    __shared__ float s_dyn, s_cap0, s_logp;
    __shared__ int s_idx, s_cnt;

    const int t = threadIdx.x, b = blockIdx.x;
    const int j = t & 127, half = t >> 7;
    const int w = t >> 5, lane = t & 31;

    const float4* E4 = (const float4*)(enc + (size_t)b * Nq * 128);
    const int nbase = half ? 51 : 0;
    const int ncnt  = half ? 50 : 51;
    float acc[13];

    // ---- Phase V: Vtmp[n][o] into KT area, then per-lane pickup -----------
    for (int c0 = 0; c0 < ncnt; c0 += 13) {
        int cn = ncnt - c0; if (cn > 13) cn = 13;
        mm13(E4, Wv + j, nbase + c0, cn, acc);
        for (int r = 0; r < cn; r++) KT[(nbase + c0 + r) * 128 + j] = acc[r];
    }
    __syncthreads();
    // vr[i]: V[n][o] with o = 16w + (lane&15), n = (lane>>4)*52 + i
    float vr[52];
    {
        const int o = w * 16 + (lane & 15);
        const int nb0 = (lane >> 4) * 52;
#pragma unroll
        for (int i = 0; i < 52; i++) {
            int n = nb0 + i;
            vr[i] = (n < Nq) ? KT[n * 128 + o] : 0.f;
        }
    }
    __syncthreads();

    // ---- Phase Kp2: Kp2T[d][n] into KT area, then per-lane pickup ---------
    for (int c0 = 0; c0 < ncnt; c0 += 13) {
        int cn = ncnt - c0; if (cn > 13) cn = 13;
        mm13(E4, g_Wpk2 + j, nbase + c0, cn, acc);
        for (int r = 0; r < cn; r++) KT[j * NP + (nbase + c0 + r)] = acc[r];
    }
    if (t < 128) { KT[t * NP + 101] = 0.f; KT[t * NP + 102] = 0.f; KT[t * NP + 103] = 0.f; }
    __syncthreads();
    float4 kp2r4[16];
    {
        const float4* K4 = (const float4*)KT;
        if (lane < 26) {
#pragma unroll
            for (int r = 0; r < 16; r++) kp2r4[r] = K4[(w * 16 + r) * 26 + lane];
        } else {
#pragma unroll
            for (int r = 0; r < 16; r++) kp2r4[r] = make_float4(0.f, 0.f, 0.f, 0.f);
        }
    }
    __syncthreads();

    // ---- Phase K: K^T[d][n] final resident --------------------------------
    for (int c0 = 0; c0 < ncnt; c0 += 13) {
        int cn = ncnt - c0; if (cn > 13) cn = 13;
        mm13(E4, Wk + j, nbase + c0, cn, acc);
        for (int r = 0; r < cn; r++) KT[j * NP + (nbase + c0 + r)] = acc[r];
    }
    if (t < 128) { KT[t * NP + 101] = 0.f; KT[t * NP + 102] = 0.f; KT[t * NP + 103] = 0.f; }

    // ---- Phase G: g_G[b][n][:] = E @ Wfw[:128] ----------------------------
    {
        float* gout = g_G + (size_t)b * Nq * 128;
        for (int c0 = 0; c0 < ncnt; c0 += 13) {
            int cn = ncnt - c0; if (cn > 13) cn = 13;
            mm13(E4, g_Wfw + j, nbase + c0, cn, acc);
            for (int r = 0; r < cn; r++) gout[(size_t)(nbase + c0 + r) * 128 + j] = acc[r];
        }
    }

    // ---- init state -------------------------------------------------------
    if (t == 0) {
        s_cap0 = capc[0]; s_dyn = capc[b]; s_logp = 0.f; s_cnt = 0; s_idx = 0;
    }
    if (t < NP) dem_s[t] = (t < Nq) ? demand[b * Nq + t] : 1e30f;
    __syncthreads();
    if (t < NP) {
        mask1A[t] = (t == 0 || t >= Nq) ? 1 : 0;
        maskA[t]  = (t == 0 || t >= Nq || dem_s[t] > s_dyn) ? 1 : 0;
    }
    __syncthreads();

    const float4* KT4 = (const float4*)KT;
    const float4* vA4 = (const float4*)vA;
    float4* comp4 = (float4*)comp;
    float4* redE4 = (float4*)redE;
    const float* gG  = g_G + (size_t)b * Nq * 128;
    const float* gPW = g_poolW + (size_t)b * Tq * 128;

    // per-lane Q constants (lanes 0-15 of each warp own dim o = 16w+lane)
    const int oq = w * 16 + (lane & 15);
    float wdyn = g_Wfw[128 * 128 + oq];
    float pw   = gPW[oq];

    // =========================== step loop =================================
    for (int step = 0; step < Tq; step++) {
        // ---- Q slice (lanes 0-15 per warp) --------------------------------
        if (lane < 16) {
            float gq = gG[(size_t)s_idx * 128 + oq];
            vA[oq] = (gq + s_dyn * wdyn + pw) * 0.25f;
            int sn = step + 1; if (sn >= Tq) sn = Tq - 1;
            pw = gPW[(size_t)sn * 128 + oq];
        }
        __syncwarp();

        // ---- compat + masked softmax (in-warp, head w) --------------------
        {
            float4 a4 = make_float4(0.f, 0.f, 0.f, 0.f);
            if (lane < 26) {
#pragma unroll
                for (int d4 = 0; d4 < 4; d4++) {
                    float4 q = vA4[w * 4 + d4];
                    float4 k0 = KT4[(w * 16 + d4 * 4 + 0) * 26 + lane];
                    float4 k1 = KT4[(w * 16 + d4 * 4 + 1) * 26 + lane];
                    float4 k2 = KT4[(w * 16 + d4 * 4 + 2) * 26 + lane];
                    float4 k3 = KT4[(w * 16 + d4 * 4 + 3) * 26 + lane];
                    a4.x += q.x*k0.x + q.y*k1.x + q.z*k2.x + q.w*k3.x;
                    a4.y += q.x*k0.y + q.y*k1.y + q.z*k2.y + q.w*k3.y;
                    a4.z += q.x*k0.z + q.y*k1.z + q.z*k2.z + q.w*k3.z;
                    a4.w += q.x*k0.w + q.y*k1.w + q.z*k2.w + q.w*k3.w;
                }
            }
            uchar4 m4 = make_uchar4(1, 1, 1, 1);
            if (lane < 26) m4 = *(const uchar4*)(maskA + 4 * lane);
            float v0 = m4.x ? -INFINITY : a4.x;
            float v1 = m4.y ? -INFINITY : a4.y;
            float v2 = m4.z ? -INFINITY : a4.z;
            float v3 = m4.w ? -INFINITY : a4.w;
            float mx = fmaxf(fmaxf(v0, v1), fmaxf(v2, v3));
#pragma unroll
            for (int o = 16; o; o >>= 1) mx = fmaxf(mx, __shfl_xor_sync(0xffffffffu, mx, o));
            float e0 = (v0 == -INFINITY) ? 0.f : expf(v0 - mx);
            float e1 = (v1 == -INFINITY) ? 0.f : expf(v1 - mx);
            float e2 = (v2 == -INFINITY) ? 0.f : expf(v2 - mx);
            float e3 = (v3 == -INFINITY) ? 0.f : expf(v3 - mx);
            float s = e0 + e1 + e2 + e3;
#pragma unroll
            for (int o = 16; o; o >>= 1) s += __shfl_xor_sync(0xffffffffu, s, o);
            float inv = 1.f / s;
            if (lane < 26)
                comp4[w * 27 + lane] = make_float4(e0 * inv, e1 * inv, e2 * inv, e3 * inv);
        }
        __syncwarp();

        // ---- glimpse (in-warp): out dims [16w,16w+16), V in regs ----------
        {
            const int cb = (lane >> 4) * 13;       // comp chunk base for my n-half
            float g = 0.f;
#pragma unroll
            for (int c = 0; c < 13; c++) {
                float4 sc = comp4[w * 27 + cb + c];
                g += sc.x * vr[4*c] + sc.y * vr[4*c+1] + sc.z * vr[4*c+2] + sc.w * vr[4*c+3];
            }
            g += __shfl_xor_sync(0xffffffffu, g, 16);
            if (lane < 16) vA[oq] = g;             // glimpse_pre slice w
        }
        __syncwarp();

        // ---- logits partial (own vA slice, Kp2 in regs) -------------------
        if (lane < 26) {
            float4 a4 = make_float4(0.f, 0.f, 0.f, 0.f);
#pragma unroll
            for (int d4 = 0; d4 < 4; d4++) {
                float4 q = vA4[w * 4 + d4];
                float4 k0 = kp2r4[d4 * 4 + 0];
                float4 k1 = kp2r4[d4 * 4 + 1];
                float4 k2 = kp2r4[d4 * 4 + 2];
                float4 k3 = kp2r4[d4 * 4 + 3];
                a4.x += q.x*k0.x + q.y*k1.x + q.z*k2.x + q.w*k3.x;
                a4.y += q.x*k0.y + q.y*k1.y + q.z*k2.y + q.w*k3.y;
                a4.z += q.x*k0.z + q.y*k1.z + q.z*k2.z + q.w*k3.z;
                a4.w += q.x*k0.w + q.y*k1.w + q.z*k2.w + q.w*k3.w;
            }
            redE4[w * 27 + lane] = a4;
        }
        __syncthreads();                                              // bar C

        // ---- reduce + tanh (t < NP) ---------------------------------------
        if (t < NP) {
            float s = redE[t];
#pragma unroll
            for (int k = 1; k < 8; k++) s += redE[k * NPC + t];
            float c2 = s * 0.08838834764831845f;
            logits[t] = maskA[t] ? -INFINITY : 10.f * tanhf(c2);
        }
        __syncthreads();                                              // bar D

        // ---- argmax + lse + state + mask update (warp 0) ------------------
        if (t < 32) {
            float bv = -INFINITY; int bi = NP;
#pragma unroll
            for (int k = 0; k < 4; k++) {
                int n = t + 32 * k;
                if (n < NP) {
                    float v = logits[n];
                    if (v > bv || (v == bv && n < bi)) { bv = v; bi = n; }
                }
            }
#pragma unroll
            for (int o = 16; o; o >>= 1) {
                float ov = __shfl_xor_sync(0xffffffffu, bv, o);
                int   oi = __shfl_xor_sync(0xffffffffu, bi, o);
                if (ov > bv || (ov == bv && oi < bi)) { bv = ov; bi = oi; }
            }
            float s = 0.f;
#pragma unroll
            for (int k = 0; k < 4; k++) {
                int n = t + 32 * k;
                if (n < NP) {
                    float v = logits[n];
                    s += (v == -INFINITY) ? 0.f : expf(v - bv);
                }
            }
#pragma unroll
            for (int o = 16; o; o >>= 1) s += __shfl_xor_sync(0xffffffffu, s, o);

            float nd = (bi == 0) ? s_cap0 : (s_dyn - dem_s[bi]);
            if (t == 0) {
                if (s_cnt < Nq - 1) s_logp += -logf(s);
                out[b * Tq + step] = (float)bi;
                s_idx = bi; s_dyn = nd;
                mask1A[0] = (bi == 0) ? 1 : 0;
            }
            __syncwarp();
            if (bi > 0 && t == (bi & 31)) {
                if (!mask1A[bi]) { mask1A[bi] = 1; s_cnt++; }
            }
            __syncwarp();
            int open = 0;
#pragma unroll
            for (int k = 0; k < 4; k++) {
                int n = t + 32 * k;
                if (n < NP) {
                    int m = (mask1A[n] || dem_s[n] > nd) ? 1 : 0;
                    maskA[n] = (unsigned char)m;
                    open |= (!m);
                }
            }
            unsigned bal = __ballot_sync(0xffffffffu, open);
            if (t == 0 && bal == 0) maskA[0] = 0;
        }
        __syncthreads();                                              // bar E
    }

    if (t == 0) out[Bq * Tq + b] = s_logp;
}

// ---------------------------------------------------------------------------
extern "C" void kernel_launch(void* const* d_in, const int* in_sizes, int n_in,
                              void* d_out, int out_size) {
    const float *enc = nullptr, *pool = nullptr, *capc = nullptr, *dem = nullptr, *Wfc = nullptr;
    const float* w16[8] = {nullptr};
    int nw = 0;
    for (int i = 0; i < n_in; i++) {
        int s = in_sizes[i];
        if      (s == Bq * Nq * 128) enc  = (const float*)d_in[i];
        else if (s == Bq * Hq)       pool = (const float*)d_in[i];
        else if (s == Bq)            capc = (const float*)d_in[i];
        else if (s == Bq * Nq)       dem  = (const float*)d_in[i];
        else if (s == (Hq + 1) * Hq) Wfc  = (const float*)d_in[i];
        else if (s == Hq * Hq) { if (nw < 8) w16[nw++] = (const float*)d_in[i]; }
    }
    // dict order among 128x128: W_fc1, W_w, W_k, W_v, W_attnfc, W_pk
    const float* Wfc1 = w16[0];
    const float* Ww   = w16[1];
    const float* Wk   = w16[2];
    const float* Wv   = w16[3];
    const float* Wat  = w16[4];
    const float* Wpk  = w16[5];

    const int smem_main = (13312 + 864 + 864) * (int)sizeof(float);   // 60160 B
    cudaFuncSetAttribute(decoder_main, cudaFuncAttributeMaxDynamicSharedMemorySize, smem_main);

    precomp0<<<257, 128>>>(Wfc, Ww, Wat, Wpk);
    precomp2<<<Bq / 2, 256>>>(pool, Wfc1, Ww);
    decoder_main<<<Bq, 256, smem_main>>>(enc, capc, dem, Wk, Wv, (float*)d_out);
}

// round 8
// speedup vs baseline: 4.4440x; 1.0660x over previous
#include <cuda_runtime.h>
#include <cuda_bf16.h>
#include <math.h>

#define Bq 512
#define Nq 101
#define Hq 128
#define Tq 140
#define NP 104
#define VSTRIDE 132

// __device__ scratch
__device__ float g_Wfw [129 * 128];                 // Wfc @ Ww
__device__ float g_Wpk2[128 * 128];                 // Wpk @ Wat^T   [k][o]
__device__ float g_poolW[(size_t)Bq * Tq * 128];    // pool@Wfc1^(s+1)@Ww  [b][s][:]
__device__ float g_G[(size_t)Bq * Nq * 128];        // enc@Wfw[:128]       [b][n][:]

// ---------------------------------------------------------------------------
// P0: fold weights
// ---------------------------------------------------------------------------
__global__ void precomp0(const float* __restrict__ Wfc, const float* __restrict__ Ww,
                         const float* __restrict__ Wat, const float* __restrict__ Wpk) {
    __shared__ __align__(16) float row[128];
    const int t = threadIdx.x, bidx = blockIdx.x;
    if (bidx < 129) {
        row[t] = Wfc[bidx * 128 + t];
        __syncthreads();
        const float4* r4 = (const float4*)row;
        float a = 0.f;
        for (int k4 = 0; k4 < 32; k4++) {
            float4 r = r4[k4];
            a += r.x * Ww[(4 * k4 + 0) * 128 + t] + r.y * Ww[(4 * k4 + 1) * 128 + t]
               + r.z * Ww[(4 * k4 + 2) * 128 + t] + r.w * Ww[(4 * k4 + 3) * 128 + t];
        }
        g_Wfw[bidx * 128 + t] = a;
    } else {
        const int d = bidx - 129;
        row[t] = Wpk[d * 128 + t];
        __syncthreads();
        const float4* r4 = (const float4*)row;
        const float4* w4 = (const float4*)(Wat + t * 128);
        float a = 0.f;
        for (int k4 = 0; k4 < 32; k4++) {
            float4 r = r4[k4]; float4 wv = w4[k4];
            a += r.x * wv.x + r.y * wv.y + r.z * wv.z + r.w * wv.w;
        }
        g_Wpk2[d * 128 + t] = a;
    }
}

// ---------------------------------------------------------------------------
// P2: pool chain folded through Ww. 2 batches/block.
// ---------------------------------------------------------------------------
__global__ __launch_bounds__(256)
void precomp2(const float* __restrict__ pool, const float* __restrict__ Wfc1,
              const float* __restrict__ Ww) {
    __shared__ __align__(16) float pA[128], pB[128];
    __shared__ float red2[256], red3[256];
    const int t = threadIdx.x, j = t & 127, kh = t >> 7;
    const int b0 = blockIdx.x * 2;
    float wf[64], wq[64];
#pragma unroll
    for (int k = 0; k < 64; k++) {
        wf[k] = Wfc1[(kh * 64 + k) * 128 + j];
        wq[k] = Ww  [(kh * 64 + k) * 128 + j];
    }
    if (t < 128) { pA[t] = pool[b0 * 128 + t]; pB[t] = pool[(b0 + 1) * 128 + t]; }
    __syncthreads();
    for (int s = 0; s < Tq; s++) {
        const float4* pa4 = (const float4*)pA; const float4* pb4 = (const float4*)pB;
        float a0 = 0.f, a1 = 0.f;
#pragma unroll
        for (int k4 = 0; k4 < 16; k4++) {
            float4 xa = pa4[kh * 16 + k4], xb = pb4[kh * 16 + k4];
            a0 += xa.x * wf[4*k4] + xa.y * wf[4*k4+1] + xa.z * wf[4*k4+2] + xa.w * wf[4*k4+3];
            a1 += xb.x * wf[4*k4] + xb.y * wf[4*k4+1] + xb.z * wf[4*k4+2] + xb.w * wf[4*k4+3];
        }
        red2[t] = a0; red3[t] = a1;
        __syncthreads();
        if (t < 128) { pA[t] = red2[t] + red2[t + 128]; pB[t] = red3[t] + red3[t + 128]; }
        __syncthreads();
        a0 = 0.f; a1 = 0.f;
#pragma unroll
        for (int k4 = 0; k4 < 16; k4++) {
            float4 xa = pa4[kh * 16 + k4], xb = pb4[kh * 16 + k4];
            a0 += xa.x * wq[4*k4] + xa.y * wq[4*k4+1] + xa.z * wq[4*k4+2] + xa.w * wq[4*k4+3];
            a1 += xb.x * wq[4*k4] + xb.y * wq[4*k4+1] + xb.z * wq[4*k4+2] + xb.w * wq[4*k4+3];
        }
        red2[t] = a0; red3[t] = a1;
        __syncthreads();
        if (t < 128) {
            g_poolW[((size_t)b0 * Tq + s) * 128 + t]       = red2[t] + red2[t + 128];
            g_poolW[((size_t)(b0 + 1) * Tq + s) * 128 + t] = red3[t] + red3[t + 128];
        }
        __syncthreads();
    }
}

// ---------------------------------------------------------------------------
// prologue matmul: 13-row chunk of one output column; E from global (bcast)
// ---------------------------------------------------------------------------
__device__ __forceinline__ void mm13(const float4* __restrict__ E4,
                                     const float* __restrict__ Wj,
                                     int n0, int cn, float* acc) {
#pragma unroll
    for (int r = 0; r < 13; r++) acc[r] = 0.f;
#pragma unroll 2
    for (int d4 = 0; d4 < 32; d4++) {
        float w0 = Wj[(4 * d4 + 0) * 128], w1 = Wj[(4 * d4 + 1) * 128];
        float w2 = Wj[(4 * d4 + 2) * 128], w3 = Wj[(4 * d4 + 3) * 128];
#pragma unroll
        for (int r = 0; r < 13; r++) if (r < cn) {
            float4 e = E4[(n0 + r) * 32 + d4];
            acc[r] = fmaf(e.x, w0, fmaf(e.y, w1, fmaf(e.z, w2, fmaf(e.w, w3, acc[r]))));
        }
    }
}

// ---------------------------------------------------------------------------
// Main decoder: 1 block / batch row, 256 threads, 2 CTAs/SM, no spills.
// ---------------------------------------------------------------------------
__global__ __launch_bounds__(256, 2)
void decoder_main(const float* __restrict__ enc, const float* __restrict__ capc,
                  const float* __restrict__ demand, const float* __restrict__ Wk,
                  const float* __restrict__ Wv, float* __restrict__ out) {
    extern __shared__ __align__(16) float sm[];
    float* KT  = sm;                 // 128*104  K^T [d][n] (also Kp2 staging)
    float* Vp  = sm + 13312;         // 104*132  V [n][o] padded
    float* cre = sm + 13312 + 13728; // 8*108  comp (softmax) / redE (shared)
    __shared__ __align__(16) float vA[128];
    __shared__ float logits[NP];
    __shared__ float dem_s[NP];
    __shared__ __align__(4) unsigned char maskA[NP], mask1A[NP];
    __shared__ float s_dyn, s_cap0, s_logp;
    __shared__ int s_idx, s_cnt;

    const int t = threadIdx.x, b = blockIdx.x;
    const int j = t & 127, half = t >> 7;
    const int w = t >> 5, lane = t & 31;

    const float4* E4 = (const float4*)(enc + (size_t)b * Nq * 128);
    const int nbase = half ? 51 : 0;
    const int ncnt  = half ? 50 : 51;
    float acc[13];

    // ---- Phase Kp2: stage Kp2T[d][n] in KT, pick up to registers ----------
    for (int c0 = 0; c0 < ncnt; c0 += 13) {
        int cn = ncnt - c0; if (cn > 13) cn = 13;
        mm13(E4, g_Wpk2 + j, nbase + c0, cn, acc);
        for (int r = 0; r < cn; r++) KT[j * NP + (nbase + c0 + r)] = acc[r];
    }
    if (t < 128) { KT[t * NP + 101] = 0.f; KT[t * NP + 102] = 0.f; KT[t * NP + 103] = 0.f; }
    __syncthreads();
    float4 kp2r4[16];
    {
        const float4* K4 = (const float4*)KT;
        if (lane < 26) {
#pragma unroll
            for (int r = 0; r < 16; r++) kp2r4[r] = K4[(w * 16 + r) * 26 + lane];
        } else {
#pragma unroll
            for (int r = 0; r < 16; r++) kp2r4[r] = make_float4(0.f, 0.f, 0.f, 0.f);
        }
    }
    __syncthreads();

    // ---- Phase V: V[n][o] direct into padded Vp ---------------------------
    for (int c0 = 0; c0 < ncnt; c0 += 13) {
        int cn = ncnt - c0; if (cn > 13) cn = 13;
        mm13(E4, Wv + j, nbase + c0, cn, acc);
        for (int r = 0; r < cn; r++) Vp[(nbase + c0 + r) * VSTRIDE + j] = acc[r];
    }
    if (t < 128) {
        Vp[101 * VSTRIDE + t] = 0.f; Vp[102 * VSTRIDE + t] = 0.f; Vp[103 * VSTRIDE + t] = 0.f;
    }

    // ---- Phase K: K^T[d][n] final resident in KT --------------------------
    for (int c0 = 0; c0 < ncnt; c0 += 13) {
        int cn = ncnt - c0; if (cn > 13) cn = 13;
        mm13(E4, Wk + j, nbase + c0, cn, acc);
        for (int r = 0; r < cn; r++) KT[j * NP + (nbase + c0 + r)] = acc[r];
    }
    if (t < 128) { KT[t * NP + 101] = 0.f; KT[t * NP + 102] = 0.f; KT[t * NP + 103] = 0.f; }

    // ---- Phase G: g_G[b][n][:] = E @ Wfw[:128] ----------------------------
    {
        float* gout = g_G + (size_t)b * Nq * 128;
        for (int c0 = 0; c0 < ncnt; c0 += 13) {
            int cn = ncnt - c0; if (cn > 13) cn = 13;
            mm13(E4, g_Wfw + j, nbase + c0, cn, acc);
            for (int r = 0; r < cn; r++) gout[(size_t)(nbase + c0 + r) * 128 + j] = acc[r];
        }
    }

    // ---- init state -------------------------------------------------------
    if (t == 0) {
        s_cap0 = capc[0]; s_dyn = capc[b]; s_logp = 0.f; s_cnt = 0; s_idx = 0;
    }
    if (t < NP) dem_s[t] = (t < Nq) ? demand[b * Nq + t] : 1e30f;
    __syncthreads();
    if (t < NP) {
        mask1A[t] = (t == 0 || t >= Nq) ? 1 : 0;
        maskA[t]  = (t == 0 || t >= Nq || dem_s[t] > s_dyn) ? 1 : 0;
    }
    __syncthreads();

    const float4* KT4 = (const float4*)KT;
    const float4* vA4 = (const float4*)vA;
    float4* cre4 = (float4*)cre;
    const float* gG  = g_G + (size_t)b * Nq * 128;
    const float* gPW = g_poolW + (size_t)b * Tq * 128;

    const int oq = w * 16 + (lane & 15);       // this lane's output dim
    const int ng = lane >> 4;                  // n-half for glimpse
    float wdyn = g_Wfw[128 * 128 + oq];
    float pw   = gPW[oq];

    // =========================== step loop =================================
    for (int step = 0; step < Tq; step++) {
        // ---- Q slice (lanes 0-15 per warp) --------------------------------
        if (lane < 16) {
            float gq = gG[(size_t)s_idx * 128 + oq];
            vA[oq] = (gq + s_dyn * wdyn + pw) * 0.25f;
            int sn = step + 1; if (sn >= Tq) sn = Tq - 1;
            pw = gPW[(size_t)sn * 128 + oq];
        }
        __syncwarp();

        // ---- compat + masked softmax (in-warp, head w) --------------------
        {
            float4 a4 = make_float4(0.f, 0.f, 0.f, 0.f);
            if (lane < 26) {
#pragma unroll
                for (int d4 = 0; d4 < 4; d4++) {
                    float4 q = vA4[w * 4 + d4];
                    float4 k0 = KT4[(w * 16 + d4 * 4 + 0) * 26 + lane];
                    float4 k1 = KT4[(w * 16 + d4 * 4 + 1) * 26 + lane];
                    float4 k2 = KT4[(w * 16 + d4 * 4 + 2) * 26 + lane];
                    float4 k3 = KT4[(w * 16 + d4 * 4 + 3) * 26 + lane];
                    a4.x += q.x*k0.x + q.y*k1.x + q.z*k2.x + q.w*k3.x;
                    a4.y += q.x*k0.y + q.y*k1.y + q.z*k2.y + q.w*k3.y;
                    a4.z += q.x*k0.z + q.y*k1.z + q.z*k2.z + q.w*k3.z;
                    a4.w += q.x*k0.w + q.y*k1.w + q.z*k2.w + q.w*k3.w;
                }
            }
            uchar4 m4 = make_uchar4(1, 1, 1, 1);
            if (lane < 26) m4 = *(const uchar4*)(maskA + 4 * lane);
            float v0 = m4.x ? -INFINITY : a4.x;
            float v1 = m4.y ? -INFINITY : a4.y;
            float v2 = m4.z ? -INFINITY : a4.z;
            float v3 = m4.w ? -INFINITY : a4.w;
            float mx = fmaxf(fmaxf(v0, v1), fmaxf(v2, v3));
#pragma unroll
            for (int o = 16; o; o >>= 1) mx = fmaxf(mx, __shfl_xor_sync(0xffffffffu, mx, o));
            float e0 = (v0 == -INFINITY) ? 0.f : expf(v0 - mx);
            float e1 = (v1 == -INFINITY) ? 0.f : expf(v1 - mx);
            float e2 = (v2 == -INFINITY) ? 0.f : expf(v2 - mx);
            float e3 = (v3 == -INFINITY) ? 0.f : expf(v3 - mx);
            float s = e0 + e1 + e2 + e3;
#pragma unroll
            for (int o = 16; o; o >>= 1) s += __shfl_xor_sync(0xffffffffu, s, o);
            float inv = 1.f / s;
            if (lane < 26)
                cre4[w * 27 + lane] = make_float4(e0 * inv, e1 * inv, e2 * inv, e3 * inv);
        }
        __syncwarp();

        // ---- glimpse (in-warp): dims [16w,16w+16), V from padded smem -----
        {
            const float* vp = Vp + ng * 52 * VSTRIDE + oq;
            const float4* cw = cre4 + w * 27 + ng * 13;
            float g = 0.f;
#pragma unroll
            for (int c = 0; c < 13; c++) {
                float4 sc = cw[c];
                g += sc.x * vp[(4*c+0)*VSTRIDE] + sc.y * vp[(4*c+1)*VSTRIDE]
                   + sc.z * vp[(4*c+2)*VSTRIDE] + sc.w * vp[(4*c+3)*VSTRIDE];
            }
            g += __shfl_xor_sync(0xffffffffu, g, 16);
            if (lane < 16) vA[oq] = g;         // glimpse_pre slice w
        }
        __syncwarp();

        // ---- logits partial (own vA slice, Kp2 in regs) -> cre (reuse) ----
        if (lane < 26) {
            float4 a4 = make_float4(0.f, 0.f, 0.f, 0.f);
#pragma unroll
            for (int d4 = 0; d4 < 4; d4++) {
                float4 q = vA4[w * 4 + d4];
                float4 k0 = kp2r4[d4 * 4 + 0];
                float4 k1 = kp2r4[d4 * 4 + 1];
                float4 k2 = kp2r4[d4 * 4 + 2];
                float4 k3 = kp2r4[d4 * 4 + 3];
                a4.x += q.x*k0.x + q.y*k1.x + q.z*k2.x + q.w*k3.x;
                a4.y += q.x*k0.y + q.y*k1.y + q.z*k2.y + q.w*k3.y;
                a4.z += q.x*k0.z + q.y*k1.z + q.z*k2.z + q.w*k3.z;
                a4.w += q.x*k0.w + q.y*k1.w + q.z*k2.w + q.w*k3.w;
            }
            cre4[w * 27 + lane] = a4;
        }
        __syncthreads();                                              // bar C

        // ---- reduce + tanh ------------------------------------------------
        if (t < NP) {
            float s = cre[t];
#pragma unroll
            for (int k = 1; k < 8; k++) s += cre[k * 108 + t];
            float c2 = s * 0.08838834764831845f;
            logits[t] = maskA[t] ? -INFINITY : 10.f * tanhf(c2);
        }
        __syncthreads();                                              // bar D

        // ---- argmax + lse + state + mask update (warp 0) ------------------
        if (t < 32) {
            float bv = -INFINITY; int bi = NP;
#pragma unroll
            for (int k = 0; k < 4; k++) {
                int n = t + 32 * k;
                if (n < NP) {
                    float v = logits[n];
                    if (v > bv || (v == bv && n < bi)) { bv = v; bi = n; }
                }
            }
#pragma unroll
            for (int o = 16; o; o >>= 1) {
                float ov = __shfl_xor_sync(0xffffffffu, bv, o);
                int   oi = __shfl_xor_sync(0xffffffffu, bi, o);
                if (ov > bv || (ov == bv && oi < bi)) { bv = ov; bi = oi; }
            }
            float s = 0.f;
#pragma unroll
            for (int k = 0; k < 4; k++) {
                int n = t + 32 * k;
                if (n < NP) {
                    float v = logits[n];
                    s += (v == -INFINITY) ? 0.f : expf(v - bv);
                }
            }
#pragma unroll
            for (int o = 16; o; o >>= 1) s += __shfl_xor_sync(0xffffffffu, s, o);

            float nd = (bi == 0) ? s_cap0 : (s_dyn - dem_s[bi]);
            if (t == 0) {
                if (s_cnt < Nq - 1) s_logp += -logf(s);
                out[b * Tq + step] = (float)bi;
                s_idx = bi; s_dyn = nd;
                mask1A[0] = (bi == 0) ? 1 : 0;
            }
            __syncwarp();
            if (bi > 0 && t == (bi & 31)) {
                if (!mask1A[bi]) { mask1A[bi] = 1; s_cnt++; }
            }
            __syncwarp();
            int open = 0;
#pragma unroll
            for (int k = 0; k < 4; k++) {
                int n = t + 32 * k;
                if (n < NP) {
                    int m = (mask1A[n] || dem_s[n] > nd) ? 1 : 0;
                    maskA[n] = (unsigned char)m;
                    open |= (!m);
                }
            }
            unsigned bal = __ballot_sync(0xffffffffu, open);
            if (t == 0 && bal == 0) maskA[0] = 0;
        }
        __syncthreads();                                              // bar E
    }

    if (t == 0) out[Bq * Tq + b] = s_logp;
}

// ---------------------------------------------------------------------------
extern "C" void kernel_launch(void* const* d_in, const int* in_sizes, int n_in,
                              void* d_out, int out_size) {
    const float *enc = nullptr, *pool = nullptr, *capc = nullptr, *dem = nullptr, *Wfc = nullptr;
    const float* w16[8] = {nullptr};
    int nw = 0;
    for (int i = 0; i < n_in; i++) {
        int s = in_sizes[i];
        if      (s == Bq * Nq * 128) enc  = (const float*)d_in[i];
        else if (s == Bq * Hq)       pool = (const float*)d_in[i];
        else if (s == Bq)            capc = (const float*)d_in[i];
        else if (s == Bq * Nq)       dem  = (const float*)d_in[i];
        else if (s == (Hq + 1) * Hq) Wfc  = (const float*)d_in[i];
        else if (s == Hq * Hq) { if (nw < 8) w16[nw++] = (const float*)d_in[i]; }
    }
    // dict order among 128x128: W_fc1, W_w, W_k, W_v, W_attnfc, W_pk
    const float* Wfc1 = w16[0];
    const float* Ww   = w16[1];
    const float* Wk   = w16[2];
    const float* Wv   = w16[3];
    const float* Wat  = w16[4];
    const float* Wpk  = w16[5];

    const int smem_main = (13312 + 13728 + 864) * (int)sizeof(float);  // 111616 B
    cudaFuncSetAttribute(decoder_main, cudaFuncAttributeMaxDynamicSharedMemorySize, smem_main);

    precomp0<<<257, 128>>>(Wfc, Ww, Wat, Wpk);
    precomp2<<<Bq / 2, 256>>>(pool, Wfc1, Ww);
    decoder_main<<<Bq, 256, smem_main>>>(enc, capc, dem, Wk, Wv, (float*)d_out);
}

// round 9
// speedup vs baseline: 4.6402x; 1.0442x over previous
#include <cuda_runtime.h>
#include <cuda_bf16.h>
#include <math.h>

#define Bq 512
#define Nq 101
#define Hq 128
#define Tq 140
#define NP 104
#define VSTRIDE 132

// __device__ scratch
__device__ float g_Wfw [129 * 128];                 // Wfc @ Ww
__device__ float g_Wpk2[128 * 128];                 // Wpk @ Wat^T   [k][o]
__device__ float g_poolW[(size_t)Bq * Tq * 128];    // pool@Wfc1^(s+1)@Ww  [b][s][:]
__device__ float g_G[(size_t)Bq * Nq * 128];        // enc@Wfw[:128]       [b][n][:]

// ---------------------------------------------------------------------------
// P0: fold weights
// ---------------------------------------------------------------------------
__global__ void precomp0(const float* __restrict__ Wfc, const float* __restrict__ Ww,
                         const float* __restrict__ Wat, const float* __restrict__ Wpk) {
    __shared__ __align__(16) float row[128];
    const int t = threadIdx.x, bidx = blockIdx.x;
    if (bidx < 129) {
        row[t] = Wfc[bidx * 128 + t];
        __syncthreads();
        const float4* r4 = (const float4*)row;
        float a = 0.f;
        for (int k4 = 0; k4 < 32; k4++) {
            float4 r = r4[k4];
            a += r.x * Ww[(4 * k4 + 0) * 128 + t] + r.y * Ww[(4 * k4 + 1) * 128 + t]
               + r.z * Ww[(4 * k4 + 2) * 128 + t] + r.w * Ww[(4 * k4 + 3) * 128 + t];
        }
        g_Wfw[bidx * 128 + t] = a;
    } else {
        const int d = bidx - 129;
        row[t] = Wpk[d * 128 + t];
        __syncthreads();
        const float4* r4 = (const float4*)row;
        const float4* w4 = (const float4*)(Wat + t * 128);
        float a = 0.f;
        for (int k4 = 0; k4 < 32; k4++) {
            float4 r = r4[k4]; float4 wv = w4[k4];
            a += r.x * wv.x + r.y * wv.y + r.z * wv.z + r.w * wv.w;
        }
        g_Wpk2[d * 128 + t] = a;
    }
}

// ---------------------------------------------------------------------------
// P2: pool chain folded through Ww. 2 batches/block.
// ---------------------------------------------------------------------------
__global__ __launch_bounds__(256)
void precomp2(const float* __restrict__ pool, const float* __restrict__ Wfc1,
              const float* __restrict__ Ww) {
    __shared__ __align__(16) float pA[128], pB[128];
    __shared__ float red2[256], red3[256];
    const int t = threadIdx.x, j = t & 127, kh = t >> 7;
    const int b0 = blockIdx.x * 2;
    float wf[64], wq[64];
#pragma unroll
    for (int k = 0; k < 64; k++) {
        wf[k] = Wfc1[(kh * 64 + k) * 128 + j];
        wq[k] = Ww  [(kh * 64 + k) * 128 + j];
    }
    if (t < 128) { pA[t] = pool[b0 * 128 + t]; pB[t] = pool[(b0 + 1) * 128 + t]; }
    __syncthreads();
    for (int s = 0; s < Tq; s++) {
        const float4* pa4 = (const float4*)pA; const float4* pb4 = (const float4*)pB;
        float a0 = 0.f, a1 = 0.f;
#pragma unroll
        for (int k4 = 0; k4 < 16; k4++) {
            float4 xa = pa4[kh * 16 + k4], xb = pb4[kh * 16 + k4];
            a0 += xa.x * wf[4*k4] + xa.y * wf[4*k4+1] + xa.z * wf[4*k4+2] + xa.w * wf[4*k4+3];
            a1 += xb.x * wf[4*k4] + xb.y * wf[4*k4+1] + xb.z * wf[4*k4+2] + xb.w * wf[4*k4+3];
        }
        red2[t] = a0; red3[t] = a1;
        __syncthreads();
        if (t < 128) { pA[t] = red2[t] + red2[t + 128]; pB[t] = red3[t] + red3[t + 128]; }
        __syncthreads();
        a0 = 0.f; a1 = 0.f;
#pragma unroll
        for (int k4 = 0; k4 < 16; k4++) {
            float4 xa = pa4[kh * 16 + k4], xb = pb4[kh * 16 + k4];
            a0 += xa.x * wq[4*k4] + xa.y * wq[4*k4+1] + xa.z * wq[4*k4+2] + xa.w * wq[4*k4+3];
            a1 += xb.x * wq[4*k4] + xb.y * wq[4*k4+1] + xb.z * wq[4*k4+2] + xb.w * wq[4*k4+3];
        }
        red2[t] = a0; red3[t] = a1;
        __syncthreads();
        if (t < 128) {
            g_poolW[((size_t)b0 * Tq + s) * 128 + t]       = red2[t] + red2[t + 128];
            g_poolW[((size_t)(b0 + 1) * Tq + s) * 128 + t] = red3[t] + red3[t + 128];
        }
        __syncthreads();
    }
}

// ---------------------------------------------------------------------------
// prologue matmul: 13-row chunk of one output column; E from global (bcast)
// ---------------------------------------------------------------------------
__device__ __forceinline__ void mm13(const float4* __restrict__ E4,
                                     const float* __restrict__ Wj,
                                     int n0, int cn, float* acc) {
#pragma unroll
    for (int r = 0; r < 13; r++) acc[r] = 0.f;
#pragma unroll 2
    for (int d4 = 0; d4 < 32; d4++) {
        float w0 = Wj[(4 * d4 + 0) * 128], w1 = Wj[(4 * d4 + 1) * 128];
        float w2 = Wj[(4 * d4 + 2) * 128], w3 = Wj[(4 * d4 + 3) * 128];
#pragma unroll
        for (int r = 0; r < 13; r++) if (r < cn) {
            float4 e = E4[(n0 + r) * 32 + d4];
            acc[r] = fmaf(e.x, w0, fmaf(e.y, w1, fmaf(e.z, w2, fmaf(e.w, w3, acc[r]))));
        }
    }
}

// ---------------------------------------------------------------------------
// Main decoder: 1 block / batch row, 256 threads, 2 CTAs/SM.
// Warp-redundant decision; 2 block barriers per step; state in registers.
// ---------------------------------------------------------------------------
__global__ __launch_bounds__(256, 2)
void decoder_main(const float* __restrict__ enc, const float* __restrict__ capc,
                  const float* __restrict__ demand, const float* __restrict__ Wk,
                  const float* __restrict__ Wv, float* __restrict__ out) {
    extern __shared__ __align__(16) float sm[];
    float* KT   = sm;                 // 128*104  K^T [d][n] (also Kp2 staging)
    float* Vp   = sm + 13312;         // 104*132  V [n][o] padded
    float* comp = sm + 13312 + 13728; // 8*108 softmax probs / logit partials
    __shared__ __align__(16) float vA[128];
    __shared__ float logits[NP];
    __shared__ float lsep[2][8];

    const int t = threadIdx.x, b = blockIdx.x;
    const int j = t & 127;
    const int w = t >> 5, lane = t & 31;
    const unsigned FULL = 0xffffffffu;

    const float4* E4 = (const float4*)(enc + (size_t)b * Nq * 128);
    const int nbase = (t >> 7) ? 51 : 0;
    const int ncnt  = (t >> 7) ? 50 : 51;
    float acc[13];

    // ---- Phase Kp2: stage Kp2T[d][n] in KT, pick up to registers ----------
    for (int c0 = 0; c0 < ncnt; c0 += 13) {
        int cn = ncnt - c0; if (cn > 13) cn = 13;
        mm13(E4, g_Wpk2 + j, nbase + c0, cn, acc);
        for (int r = 0; r < cn; r++) KT[j * NP + (nbase + c0 + r)] = acc[r];
    }
    if (t < 128) { KT[t * NP + 101] = 0.f; KT[t * NP + 102] = 0.f; KT[t * NP + 103] = 0.f; }
    __syncthreads();
    float4 kp2r4[16];
    {
        const float4* K4 = (const float4*)KT;
        if (lane < 26) {
#pragma unroll
            for (int r = 0; r < 16; r++) kp2r4[r] = K4[(w * 16 + r) * 26 + lane];
        } else {
#pragma unroll
            for (int r = 0; r < 16; r++) kp2r4[r] = make_float4(0.f, 0.f, 0.f, 0.f);
        }
    }
    __syncthreads();

    // ---- Phase V: V[n][o] direct into padded Vp ---------------------------
    for (int c0 = 0; c0 < ncnt; c0 += 13) {
        int cn = ncnt - c0; if (cn > 13) cn = 13;
        mm13(E4, Wv + j, nbase + c0, cn, acc);
        for (int r = 0; r < cn; r++) Vp[(nbase + c0 + r) * VSTRIDE + j] = acc[r];
    }
    if (t < 128) {
        Vp[101 * VSTRIDE + t] = 0.f; Vp[102 * VSTRIDE + t] = 0.f; Vp[103 * VSTRIDE + t] = 0.f;
    }

    // ---- Phase K: K^T[d][n] final resident in KT --------------------------
    for (int c0 = 0; c0 < ncnt; c0 += 13) {
        int cn = ncnt - c0; if (cn > 13) cn = 13;
        mm13(E4, Wk + j, nbase + c0, cn, acc);
        for (int r = 0; r < cn; r++) KT[j * NP + (nbase + c0 + r)] = acc[r];
    }
    if (t < 128) { KT[t * NP + 101] = 0.f; KT[t * NP + 102] = 0.f; KT[t * NP + 103] = 0.f; }

    // ---- Phase G: g_G[b][n][:] = E @ Wfw[:128] ----------------------------
    {
        float* gout = g_G + (size_t)b * Nq * 128;
        for (int c0 = 0; c0 < ncnt; c0 += 13) {
            int cn = ncnt - c0; if (cn > 13) cn = 13;
            mm13(E4, g_Wfw + j, nbase + c0, cn, acc);
            for (int r = 0; r < cn; r++) gout[(size_t)(nbase + c0 + r) * 128 + j] = acc[r];
        }
    }
    __syncthreads();   // all tiles + g_G ready

    // ---- warp-private register state --------------------------------------
    const float cap0 = capc[0];
    float dyn = capc[b];
    float dem4[4];
    unsigned m1b = 0;          // bit k: mask1 for n = lane + 32k
#pragma unroll
    for (int k = 0; k < 4; k++) {
        int n = lane + 32 * k;
        dem4[k] = (n < Nq) ? demand[b * Nq + n] : 1e30f;
        if (n == 0 || n >= Nq) m1b |= (1u << k);
    }
    unsigned mw[4];            // warp-uniform mask words (bit n%32 of word n/32)
    {
        unsigned allm = 0xffffffffu;
#pragma unroll
        for (int k = 0; k < 4; k++) {
            int mk = ((m1b >> k) & 1) || (dem4[k] > dyn);
            mw[k] = __ballot_sync(FULL, mk);
            allm &= mw[k];
        }
        if (allm == 0xffffffffu) mw[0] &= ~1u;
    }
    int bi = 0, cnt = 0, pg = 1, par = 0;
    float logp = 0.f;

    const float4* KT4 = (const float4*)KT;
    const float4* vA4 = (const float4*)vA;
    float4* comp4 = (float4*)comp;
    const float* gG  = g_G + (size_t)b * Nq * 128;
    const float* gPW = g_poolW + (size_t)b * Tq * 128;

    const int oq = w * 16 + (lane & 15);
    const int ng = lane >> 4;
    const float wdyn = g_Wfw[128 * 128 + oq];
    float pw = gPW[oq];
    float qv = gG[oq];         // G row for initial index 0

    // =========================== step loop =================================
    for (int step = 0; step < Tq; step++) {
        // ---- Q slice (lanes 0-15 per warp); qv preloaded ------------------
        if (lane < 16) {
            vA[oq] = (qv + dyn * wdyn + pw) * 0.25f;
            int sn = step + 1; if (sn >= Tq) sn = Tq - 1;
            pw = gPW[(size_t)sn * 128 + oq];
        }
        __syncwarp();

        // ---- compat + masked softmax (in-warp, head w) --------------------
        {
            float4 a4 = make_float4(0.f, 0.f, 0.f, 0.f);
            if (lane < 26) {
#pragma unroll
                for (int d4 = 0; d4 < 4; d4++) {
                    float4 q = vA4[w * 4 + d4];
                    float4 k0 = KT4[(w * 16 + d4 * 4 + 0) * 26 + lane];
                    float4 k1 = KT4[(w * 16 + d4 * 4 + 1) * 26 + lane];
                    float4 k2 = KT4[(w * 16 + d4 * 4 + 2) * 26 + lane];
                    float4 k3 = KT4[(w * 16 + d4 * 4 + 3) * 26 + lane];
                    a4.x += q.x*k0.x + q.y*k1.x + q.z*k2.x + q.w*k3.x;
                    a4.y += q.x*k0.y + q.y*k1.y + q.z*k2.y + q.w*k3.y;
                    a4.z += q.x*k0.z + q.y*k1.z + q.z*k2.z + q.w*k3.z;
                    a4.w += q.x*k0.w + q.y*k1.w + q.z*k2.w + q.w*k3.w;
                }
            }
            unsigned nib = (mw[lane >> 3] >> ((lane & 7) * 4)) & 0xFu;
            if (lane >= 26) nib = 0xFu;
            float v0 = (nib & 1u) ? -INFINITY : a4.x;
            float v1 = (nib & 2u) ? -INFINITY : a4.y;
            float v2 = (nib & 4u) ? -INFINITY : a4.z;
            float v3 = (nib & 8u) ? -INFINITY : a4.w;
            float mx = fmaxf(fmaxf(v0, v1), fmaxf(v2, v3));
#pragma unroll
            for (int o = 16; o; o >>= 1) mx = fmaxf(mx, __shfl_xor_sync(FULL, mx, o));
            float e0 = (v0 == -INFINITY) ? 0.f : expf(v0 - mx);
            float e1 = (v1 == -INFINITY) ? 0.f : expf(v1 - mx);
            float e2 = (v2 == -INFINITY) ? 0.f : expf(v2 - mx);
            float e3 = (v3 == -INFINITY) ? 0.f : expf(v3 - mx);
            float s = e0 + e1 + e2 + e3;
#pragma unroll
            for (int o = 16; o; o >>= 1) s += __shfl_xor_sync(FULL, s, o);
            float inv = 1.f / s;
            if (lane < 26)
                comp4[w * 27 + lane] = make_float4(e0 * inv, e1 * inv, e2 * inv, e3 * inv);
        }
        __syncwarp();

        // ---- glimpse (in-warp): dims [16w,16w+16), V from padded smem -----
        {
            const float* vp = Vp + ng * 52 * VSTRIDE + oq;
            const float4* cw = comp4 + w * 27 + ng * 13;
            float g = 0.f;
#pragma unroll
            for (int c = 0; c < 13; c++) {
                float4 sc = cw[c];
                g += sc.x * vp[(4*c+0)*VSTRIDE] + sc.y * vp[(4*c+1)*VSTRIDE]
                   + sc.z * vp[(4*c+2)*VSTRIDE] + sc.w * vp[(4*c+3)*VSTRIDE];
            }
            g += __shfl_xor_sync(FULL, g, 16);
            if (lane < 16) vA[oq] = g;
        }
        __syncwarp();

        // ---- logits partial (own vA slice, Kp2 in regs) -> comp row w -----
        if (lane < 26) {
            float4 a4 = make_float4(0.f, 0.f, 0.f, 0.f);
#pragma unroll
            for (int d4 = 0; d4 < 4; d4++) {
                float4 q = vA4[w * 4 + d4];
                float4 k0 = kp2r4[d4 * 4 + 0];
                float4 k1 = kp2r4[d4 * 4 + 1];
                float4 k2 = kp2r4[d4 * 4 + 2];
                float4 k3 = kp2r4[d4 * 4 + 3];
                a4.x += q.x*k0.x + q.y*k1.x + q.z*k2.x + q.w*k3.x;
                a4.y += q.x*k0.y + q.y*k1.y + q.z*k2.y + q.w*k3.y;
                a4.z += q.x*k0.z + q.y*k1.z + q.z*k2.z + q.w*k3.z;
                a4.w += q.x*k0.w + q.y*k1.w + q.z*k2.w + q.w*k3.w;
            }
            comp4[w * 27 + lane] = a4;
        }
        __syncthreads();                                              // bar C

        // ---- warp w: logits slice n in [13w, 13w+13) ----------------------
        if (lane < 13) {
            const int n = 13 * w + lane;
            float s = comp[n];
#pragma unroll
            for (int k = 1; k < 8; k++) s += comp[k * 108 + n];
            float c2 = s * 0.08838834764831845f;
            int msk = (mw[n >> 5] >> (n & 31)) & 1;
            logits[n] = msk ? -INFINITY : 10.f * tanhf(c2);
        }
        __syncthreads();                                              // bar D

        // ---- redundant argmax (every warp, identical result) --------------
        float bv = -INFINITY; int nbi = NP;
#pragma unroll
        for (int k = 0; k < 4; k++) {
            int n = lane + 32 * k;
            if (n < NP) {
                float v = logits[n];
                if (v > bv || (v == bv && n < nbi)) { bv = v; nbi = n; }
            }
        }
#pragma unroll
        for (int o = 16; o; o >>= 1) {
            float ov = __shfl_xor_sync(FULL, bv, o);
            int   oi = __shfl_xor_sync(FULL, nbi, o);
            if (ov > bv || (ov == bv && oi < nbi)) { bv = ov; nbi = oi; }
        }
        bi = nbi;                                   // warp-uniform

        // ---- early G load for next step (hides L2 latency) ----------------
        if (lane < 16) qv = gG[(size_t)bi * 128 + oq];

        // ---- warp0: fold previous step's lse partials ---------------------
        if (w == 0 && lane == 0 && step > 0 && pg) {
            float ss = lsep[par ^ 1][0] + lsep[par ^ 1][1] + lsep[par ^ 1][2]
                     + lsep[par ^ 1][3] + lsep[par ^ 1][4] + lsep[par ^ 1][5]
                     + lsep[par ^ 1][6] + lsep[par ^ 1][7];
            logp -= logf(ss);
        }
        if (w == 0 && lane == 0) out[b * Tq + step] = (float)bi;

        // ---- state update (warp-private registers) ------------------------
        {
            const int ks = bi >> 5, ls = bi & 31;
            float dv = __shfl_sync(FULL, dem4[ks], ls);
            unsigned m1o = __shfl_sync(FULL, m1b, ls);
            int was = (m1o >> ks) & 1;
            pg = (cnt < Nq - 1);
            if (bi > 0 && !was) cnt++;
            if (bi > 0 && lane == ls) m1b |= (1u << ks);
            if (lane == 0) m1b = (m1b & ~1u) | (bi == 0 ? 1u : 0u);
            dyn = (bi == 0) ? cap0 : (dyn - dv);
            unsigned allm = 0xffffffffu;
#pragma unroll
            for (int k = 0; k < 4; k++) {
                int mk = ((m1b >> k) & 1) || (dem4[k] > dyn);
                mw[k] = __ballot_sync(FULL, mk);
                allm &= mw[k];
            }
            if (allm == 0xffffffffu) mw[0] &= ~1u;
        }

        // ---- lse partial for this step (slice [13w,13w+13)) ---------------
        {
            float e = 0.f;
            if (lane < 13) {
                float v = logits[13 * w + lane];
                e = expf(v - bv);            // expf(-inf)=0 for masked
            }
#pragma unroll
            for (int o = 8; o; o >>= 1) e += __shfl_xor_sync(FULL, e, o);
            if (lane == 0) lsep[par][w] = e;
        }
        par ^= 1;
    }

    __syncthreads();
    if (w == 0 && lane == 0) {
        if (pg) {
            float ss = lsep[par ^ 1][0] + lsep[par ^ 1][1] + lsep[par ^ 1][2]
                     + lsep[par ^ 1][3] + lsep[par ^ 1][4] + lsep[par ^ 1][5]
                     + lsep[par ^ 1][6] + lsep[par ^ 1][7];
            logp -= logf(ss);
        }
        out[Bq * Tq + b] = logp;
    }
}

// ---------------------------------------------------------------------------
extern "C" void kernel_launch(void* const* d_in, const int* in_sizes, int n_in,
                              void* d_out, int out_size) {
    const float *enc = nullptr, *pool = nullptr, *capc = nullptr, *dem = nullptr, *Wfc = nullptr;
    const float* w16[8] = {nullptr};
    int nw = 0;
    for (int i = 0; i < n_in; i++) {
        int s = in_sizes[i];
        if      (s == Bq * Nq * 128) enc  = (const float*)d_in[i];
        else if (s == Bq * Hq)       pool = (const float*)d_in[i];
        else if (s == Bq)            capc = (const float*)d_in[i];
        else if (s == Bq * Nq)       dem  = (const float*)d_in[i];
        else if (s == (Hq + 1) * Hq) Wfc  = (const float*)d_in[i];
        else if (s == Hq * Hq) { if (nw < 8) w16[nw++] = (const float*)d_in[i]; }
    }
    // dict order among 128x128: W_fc1, W_w, W_k, W_v, W_attnfc, W_pk
    const float* Wfc1 = w16[0];
    const float* Ww   = w16[1];
    const float* Wk   = w16[2];
    const float* Wv   = w16[3];
    const float* Wat  = w16[4];
    const float* Wpk  = w16[5];

    const int smem_main = (13312 + 13728 + 864) * (int)sizeof(float);  // 111616 B
    cudaFuncSetAttribute(decoder_main, cudaFuncAttributeMaxDynamicSharedMemorySize, smem_main);

    precomp0<<<257, 128>>>(Wfc, Ww, Wat, Wpk);
    precomp2<<<Bq / 2, 256>>>(pool, Wfc1, Ww);
    decoder_main<<<Bq, 256, smem_main>>>(enc, capc, dem, Wk, Wv, (float*)d_out);
}